// round 13
// baseline (speedup 1.0000x reference)
#include <cuda_runtime.h>
#include <cuda_fp16.h>
#include <cstdint>

#define BB 2
#define NN 384
#define DD 768
#define EE 64
#define HH 512
#define JT 64

// -------- scratch (no allocations allowed) --------
__device__ float  g_NI [BB * NN * HH];       // 1.5 MB
__device__ __half g_NJh[BB * NN * HH];       // 768 KB
__device__ __half g_heh[BB * NN * HH];       // 768 KB
__device__ __half g_w1h[8 * 64 * 64];        // We  chunks [ch][n][k]
__device__ __half g_w2h[8 * 64 * 64];        // ew2 chunks [kc][n][k]
__device__ __half g_wijh[2 * 512 * 768];     // Wi/Wj transposed [z][n][k]

__device__ __forceinline__ uint32_t pack2(float a, float b) {
    __half2 h = __floats2half2_rn(a, b);
    return *reinterpret_cast<uint32_t*>(&h);
}
__device__ __forceinline__ float2 h2f(uint32_t u) {
    return __half22float2(*reinterpret_cast<__half2*>(&u));
}
__device__ __forceinline__ void ldm_x4(uint32_t& r0, uint32_t& r1,
                                       uint32_t& r2, uint32_t& r3, uint32_t addr) {
    asm volatile("ldmatrix.sync.aligned.m8n8.x4.shared.b16 {%0,%1,%2,%3}, [%4];"
                 : "=r"(r0), "=r"(r1), "=r"(r2), "=r"(r3) : "r"(addr));
}
__device__ __forceinline__ void mma_f16(float c[4],
                                        uint32_t a0, uint32_t a1, uint32_t a2, uint32_t a3,
                                        uint32_t b0, uint32_t b1) {
    asm volatile("mma.sync.aligned.m16n8k16.row.col.f32.f16.f16.f32 "
        "{%0,%1,%2,%3}, {%4,%5,%6,%7}, {%8,%9}, {%0,%1,%2,%3};"
        : "+f"(c[0]), "+f"(c[1]), "+f"(c[2]), "+f"(c[3])
        : "r"(a0), "r"(a1), "r"(a2), "r"(a3), "r"(b0), "r"(b1));
}
__device__ __forceinline__ void cp16(uint32_t dst, const void* src) {
    asm volatile("cp.async.cg.shared.global [%0], [%1], 16;" :: "r"(dst), "l"(src));
}
#define CP_COMMIT() asm volatile("cp.async.commit_group;" ::: "memory")
#define CP_WAIT0()  asm volatile("cp.async.wait_group 0;" ::: "memory")

// warp-tile m16 x n32 GEMM over one k=64 chunk; B stride 72 halves
__device__ __forceinline__ void gemm_16x32(uint32_t sb, int offA, int strideA, int colA,
                                           int offB, int mt, int nt, int lane,
                                           float c[4][4]) {
    const int arow = lane & 15, ak8 = (lane >> 4) << 3;
    const int bn = (lane & 7) + ((lane >> 4) << 3);
    const int bk8 = ((lane >> 3) & 1) << 3;
    #pragma unroll
    for (int ks = 0; ks < 4; ks++) {
        int k0 = ks * 16;
        uint32_t a0, a1, a2, a3, p0, p1, p2, p3, q0, q1, q2, q3;
        ldm_x4(a0, a1, a2, a3, sb + 2 * (offA + (mt + arow) * strideA + colA + k0 + ak8));
        ldm_x4(p0, p1, p2, p3, sb + 2 * (offB + (nt + bn) * 72 + k0 + bk8));
        ldm_x4(q0, q1, q2, q3, sb + 2 * (offB + (nt + 16 + bn) * 72 + k0 + bk8));
        mma_f16(c[0], a0, a1, a2, a3, p0, p1);
        mma_f16(c[1], a0, a1, a2, a3, p2, p3);
        mma_f16(c[2], a0, a1, a2, a3, q0, q1);
        mma_f16(c[3], a0, a1, a2, a3, q2, q3);
    }
}

// ============================================================
// Kernel 0: weight pre-conversion to fp16 staging layouts
// ============================================================
__global__ __launch_bounds__(256) void k_prep(const float* __restrict__ ew1,
                                              const float* __restrict__ ew2)
{
    int idx = blockIdx.x * 256 + threadIdx.x;
    int stride = gridDim.x * 256;
    for (int i = idx; i < 8 * 64 * 64; i += stride) {
        int ch = i >> 12, r = i & 4095, n = r >> 6, k = r & 63;
        g_w1h[i] = __float2half_rn(ew1[(size_t)k * HH + ch * 64 + n]);
    }
    for (int i = idx; i < 8 * 64 * 64; i += stride) {
        int kc = i >> 12, r = i & 4095, n = r >> 6, k = r & 63;
        g_w2h[i] = __float2half_rn(ew2[(size_t)(kc * 64 + k) * EE + n]);
    }
    for (int i = idx; i < 2 * 512 * 768; i += stride) {
        int z = i / (512 * 768), r = i % (512 * 768), n = r / 768, k = r % 768;
        g_wijh[i] = __float2half_rn(ew1[(size_t)(EE + z * DD + k) * HH + n]);
    }
}

// ============================================================
// Kernel 1: NI = nodes@Wi + eb1 (fp32 out); NJ = nodes@Wj (fp16 out)
// 32-row tiles, grid (8, 24) = 192 CTAs, one warp-tile per warp.
// ============================================================
#define NJ_A0 0
#define NJ_A1 (32 * 72)
#define NJ_B0 (2 * 32 * 72)
#define NJ_B1 (NJ_B0 + 128 * 72)
#define NINJ_SMEM_BYTES ((NJ_B1 + 128 * 72) * 2)

__global__ __launch_bounds__(256) void k_ninj_mma(const float* __restrict__ nodes,
                                                  const float* __restrict__ eb1)
{
    extern __shared__ __half shn[];
    const uint32_t sb = (uint32_t)__cvta_generic_to_shared(shn);
    const int tid = threadIdx.x;
    const int w = tid >> 5, lane = tid & 31;
    const int g = lane >> 2, tig = lane & 3;
    const int mt = (w & 1) * 16, ntb = (w >> 1) * 32;
    const int gc = blockIdx.x * 128;
    const int r0 = blockIdx.y * 32;
    const bool is_ni = (gc < HH);
    const int z = is_ni ? 0 : 1;
    const int col0 = is_ni ? gc : (gc - HH);
    const __half* wsrc = g_wijh + (size_t)z * 512 * 768;

    float cacc[4][4];
    #pragma unroll
    for (int nj = 0; nj < 4; nj++)
        #pragma unroll
        for (int x = 0; x < 4; x++) cacc[nj][x] = 0.f;

    // prefetch A0 to regs; issue B0 cp.async
    uint2 areg[2];
    #pragma unroll
    for (int t = 0; t < 2; t++) {
        int q = t * 256 + tid;
        int r = q >> 4, k0 = (q & 15) * 4;
        float4 v = __ldg((const float4*)&nodes[(size_t)(r0 + r) * DD + k0]);
        areg[t] = make_uint2(pack2(v.x, v.y), pack2(v.z, v.w));
    }
    #pragma unroll
    for (int t = 0; t < 4; t++) {
        int q = t * 256 + tid;                 // 1024 segs
        int n = q >> 3, k8 = (q & 7) * 8;
        cp16(sb + 2 * (NJ_B0 + n * 72 + k8), wsrc + (size_t)(col0 + n) * 768 + k8);
    }
    CP_COMMIT();

    for (int kc = 0; kc < 12; kc++) {
        const int abuf = (kc & 1) ? NJ_A1 : NJ_A0;
        #pragma unroll
        for (int t = 0; t < 2; t++) {
            int q = t * 256 + tid;
            int r = q >> 4, k0 = (q & 15) * 4;
            *(uint2*)&shn[abuf + r * 72 + k0] = areg[t];
        }
        if (kc < 11) {
            #pragma unroll
            for (int t = 0; t < 2; t++) {
                int q = t * 256 + tid;
                int r = q >> 4, k0 = (q & 15) * 4;
                float4 v = __ldg((const float4*)&nodes[(size_t)(r0 + r) * DD + (kc + 1) * 64 + k0]);
                areg[t] = make_uint2(pack2(v.x, v.y), pack2(v.z, v.w));
            }
        }
        CP_WAIT0();
        __syncthreads();
        if (kc < 11) {
            const int nb = (kc & 1) ? NJ_B0 : NJ_B1;
            #pragma unroll
            for (int t = 0; t < 4; t++) {
                int q = t * 256 + tid;
                int n = q >> 3, k8 = (q & 7) * 8;
                cp16(sb + 2 * (nb + n * 72 + k8),
                     wsrc + (size_t)(col0 + n) * 768 + (kc + 1) * 64 + k8);
            }
            CP_COMMIT();
        }
        const int bbuf = (kc & 1) ? NJ_B1 : NJ_B0;
        gemm_16x32(sb, abuf, 72, 0, bbuf, mt, ntb, lane, cacc);
        __syncthreads();
    }

    #pragma unroll
    for (int nj = 0; nj < 4; nj++) {
        int coll = ntb + nj * 8 + 2 * tig;
        #pragma unroll
        for (int rr = 0; rr < 2; rr++) {
            int row = mt + g + rr * 8;
            float v0 = cacc[nj][rr * 2 + 0];
            float v1 = cacc[nj][rr * 2 + 1];
            if (is_ni) {
                float2 e = __ldg((const float2*)&eb1[gc + coll]);
                *(float2*)&g_NI[(size_t)(r0 + row) * HH + gc + coll] =
                    make_float2(v0 + e.x, v1 + e.y);
            } else {
                *(uint32_t*)&g_NJh[(size_t)(r0 + row) * HH + col0 + coll] = pack2(v0, v1);
            }
        }
    }
}

// ============================================================
// Kernel 2: node path part 1 (unchanged)
// ============================================================
#define N1_SUM 0
#define N1_SQ  16
#define N1_MU  32
#define N1_RS  48
#define N1_AGG 64
#define N1H_A  2176
#define N1H_B  (N1H_A + 16 * 72)
#define N1_SMEM_BYTES ((N1H_B + 512 * 72) * 2)

__global__ __launch_bounds__(256) void k_node1(
    const float* __restrict__ nodes, const float* __restrict__ edges,
    const float* __restrict__ adj, const float* __restrict__ nw1,
    const float* __restrict__ nb1, const float* __restrict__ ng,
    const float* __restrict__ nbt)
{
    extern __shared__ float smem[];
    __half* sh = (__half*)smem;
    const uint32_t sb = (uint32_t)__cvta_generic_to_shared(smem);
    const int tid = threadIdx.x;
    const int w = tid >> 5, lane = tid & 31;
    const int g = lane >> 2, tig = lane & 3;
    const int r0 = blockIdx.x * 16;
    const int b = r0 / NN, i0 = r0 % NN;

    if (tid < 16) { smem[N1_SUM + tid] = 0.f; smem[N1_SQ + tid] = 0.f; }

    {
        int r = tid >> 4, e4 = (tid & 15) * 4;
        const float* er = edges + (size_t)((size_t)(b * NN + i0 + r) * NN) * EE;
        const float* ar = adj + (size_t)(b * NN + i0 + r) * NN;
        float4 acc = make_float4(0.f, 0.f, 0.f, 0.f);
        for (int j = 0; j < NN; j += 4) {
            float a0 = ar[j], a1 = ar[j + 1], a2 = ar[j + 2], a3 = ar[j + 3];
            if (a0 != 0.f) { float4 v = __ldg((const float4*)&er[(size_t)j * EE + e4]);
                acc.x += v.x * a0; acc.y += v.y * a0; acc.z += v.z * a0; acc.w += v.w * a0; }
            if (a1 != 0.f) { float4 v = __ldg((const float4*)&er[(size_t)(j + 1) * EE + e4]);
                acc.x += v.x * a1; acc.y += v.y * a1; acc.z += v.z * a1; acc.w += v.w * a1; }
            if (a2 != 0.f) { float4 v = __ldg((const float4*)&er[(size_t)(j + 2) * EE + e4]);
                acc.x += v.x * a2; acc.y += v.y * a2; acc.z += v.z * a2; acc.w += v.w * a2; }
            if (a3 != 0.f) { float4 v = __ldg((const float4*)&er[(size_t)(j + 3) * EE + e4]);
                acc.x += v.x * a3; acc.y += v.y * a3; acc.z += v.z * a3; acc.w += v.w * a3; }
        }
        *(float4*)&smem[N1_AGG + r * 64 + e4] = acc;
    }
    __syncthreads();

    float cacc[2][4][4];
    #pragma unroll
    for (int s = 0; s < 2; s++)
        #pragma unroll
        for (int nj = 0; nj < 4; nj++)
            #pragma unroll
            for (int x = 0; x < 4; x++) cacc[s][nj][x] = 0.f;

    for (int kc = 0; kc < 13; kc++) {
        __syncthreads();
        {
            int r = tid >> 4, k0 = (tid & 15) * 4;
            float4 v;
            if (kc == 0) v = *(float4*)&smem[N1_AGG + r * 64 + k0];
            else {
                v = __ldg((const float4*)&nodes[(size_t)(r0 + r) * DD + (kc - 1) * 64 + k0]);
                v.x *= (float)NN; v.y *= (float)NN; v.z *= (float)NN; v.w *= (float)NN;
            }
            *(uint2*)&sh[N1H_A + r * 72 + k0] = make_uint2(pack2(v.x, v.y), pack2(v.z, v.w));
        }
        {
            int q = tid;
            for (int t = 0; t < 32; t++, q += 256) {
                int n = q & 511, k0 = (q >> 9) * 4;
                const float* p = nw1 + (size_t)(kc * 64 + k0) * HH + n;
                *(uint2*)&sh[N1H_B + n * 72 + k0] =
                    make_uint2(pack2(__ldg(p), __ldg(p + HH)),
                               pack2(__ldg(p + 2 * HH), __ldg(p + 3 * HH)));
            }
        }
        __syncthreads();
        gemm_16x32(sb, N1H_A, 72, 0, N1H_B, 0, w * 64, lane, cacc[0]);
        gemm_16x32(sb, N1H_A, 72, 0, N1H_B, 0, w * 64 + 32, lane, cacc[1]);
    }

    float rsum[2] = {0.f, 0.f}, rsq[2] = {0.f, 0.f};
    #pragma unroll
    for (int s = 0; s < 2; s++)
        #pragma unroll
        for (int nj = 0; nj < 4; nj++) {
            int coll = w * 64 + s * 32 + nj * 8 + 2 * tig;
            float2 b1 = __ldg((const float2*)&nb1[coll]);
            #pragma unroll
            for (int rr = 0; rr < 2; rr++) {
                float v0 = cacc[s][nj][rr * 2 + 0] + b1.x;
                float v1 = cacc[s][nj][rr * 2 + 1] + b1.y;
                cacc[s][nj][rr * 2 + 0] = v0;
                cacc[s][nj][rr * 2 + 1] = v1;
                rsum[rr] += v0 + v1;
                rsq[rr]  += v0 * v0 + v1 * v1;
            }
        }
    #pragma unroll
    for (int rr = 0; rr < 2; rr++) {
        float s = rsum[rr], q2 = rsq[rr];
        s  += __shfl_xor_sync(0xffffffffu, s, 1);
        s  += __shfl_xor_sync(0xffffffffu, s, 2);
        q2 += __shfl_xor_sync(0xffffffffu, q2, 1);
        q2 += __shfl_xor_sync(0xffffffffu, q2, 2);
        if (tig == 0) {
            atomicAdd(&smem[N1_SUM + g + rr * 8], s);
            atomicAdd(&smem[N1_SQ + g + rr * 8], q2);
        }
    }
    __syncthreads();
    if (tid < 16) {
        float mu = smem[N1_SUM + tid] * (1.f / HH);
        float var = smem[N1_SQ + tid] * (1.f / HH) - mu * mu;
        smem[N1_MU + tid] = mu;
        smem[N1_RS + tid] = rsqrtf(var + 1e-5f);
    }
    __syncthreads();
    const float mu0 = smem[N1_MU + g],     rs0 = smem[N1_RS + g];
    const float mu1 = smem[N1_MU + g + 8], rs1 = smem[N1_RS + g + 8];

    #pragma unroll
    for (int s = 0; s < 2; s++)
        #pragma unroll
        for (int nj = 0; nj < 4; nj++) {
            int coll = w * 64 + s * 32 + nj * 8 + 2 * tig;
            float2 gg = __ldg((const float2*)&ng[coll]);
            float2 bb = __ldg((const float2*)&nbt[coll]);
            float v0 = fmaxf((cacc[s][nj][0] - mu0) * rs0 * gg.x + bb.x, 0.f);
            float v1 = fmaxf((cacc[s][nj][1] - mu0) * rs0 * gg.y + bb.y, 0.f);
            float v2 = fmaxf((cacc[s][nj][2] - mu1) * rs1 * gg.x + bb.x, 0.f);
            float v3 = fmaxf((cacc[s][nj][3] - mu1) * rs1 * gg.y + bb.y, 0.f);
            *(uint32_t*)&sh[N1H_B + g * 520 + coll]       = pack2(v0, v1);
            *(uint32_t*)&sh[N1H_B + (g + 8) * 520 + coll] = pack2(v2, v3);
        }
    __syncthreads();
    {
        int q = tid;
        #pragma unroll
        for (int t = 0; t < 4; t++, q += 256) {
            int r = q >> 6, c0 = (q & 63) * 8;
            *(uint4*)&g_heh[(size_t)(r0 + r) * HH + c0] = *(uint4*)&sh[N1H_B + r * 520 + c0];
        }
    }
}

// ============================================================
// Kernel 3: node path part 2 (unchanged)
// ============================================================
#define N2H_HE 0
#define N2H_B  (32 * 520)
#define N2F_OUT 12928
#define N2_SMEM_BYTES ((N2F_OUT + 32 * 132) * 4)

__global__ __launch_bounds__(256) void k_node2(
    const float* __restrict__ nodes, const float* __restrict__ nw2,
    const float* __restrict__ nb2, float* __restrict__ out_nodes)
{
    extern __shared__ float smem[];
    __half* sh = (__half*)smem;
    const uint32_t sb = (uint32_t)__cvta_generic_to_shared(smem);
    const int tid = threadIdx.x;
    const int w = tid >> 5, lane = tid & 31;
    const int g = lane >> 2, tig = lane & 3;
    const int mt = (w & 1) * 16, nt = (w >> 1) * 32;
    const int nc = blockIdx.x * 128;
    const int r0 = blockIdx.y * 32;

    {
        int q = tid;
        #pragma unroll
        for (int t = 0; t < 8; t++, q += 256) {
            int r = q >> 6, c0 = (q & 63) * 8;
            *(uint4*)&sh[N2H_HE + r * 520 + c0] = *(const uint4*)&g_heh[(size_t)(r0 + r) * HH + c0];
        }
    }

    float c2[4][4];
    #pragma unroll
    for (int nj = 0; nj < 4; nj++)
        #pragma unroll
        for (int x = 0; x < 4; x++) c2[nj][x] = 0.f;

    for (int kc = 0; kc < 8; kc++) {
        __syncthreads();
        {
            int q = tid;
            #pragma unroll
            for (int t = 0; t < 8; t++, q += 256) {
                int n = q & 127, k0 = (q >> 7) * 4;
                const float* p = nw2 + (size_t)(kc * 64 + k0) * DD + nc + n;
                *(uint2*)&sh[N2H_B + n * 72 + k0] =
                    make_uint2(pack2(__ldg(p), __ldg(p + DD)),
                               pack2(__ldg(p + 2 * DD), __ldg(p + 3 * DD)));
            }
        }
        __syncthreads();
        gemm_16x32(sb, N2H_HE, 520, kc * 64, N2H_B, mt, nt, lane, c2);
    }

    __syncthreads();
    #pragma unroll
    for (int nj = 0; nj < 4; nj++) {
        int coll = nt + nj * 8 + 2 * tig;
        #pragma unroll
        for (int rr = 0; rr < 2; rr++) {
            int row = mt + g + rr * 8;
            *(float2*)&smem[N2F_OUT + row * 132 + coll] =
                make_float2(c2[nj][rr * 2 + 0], c2[nj][rr * 2 + 1]);
        }
    }
    __syncthreads();
    {
        int q = tid;
        #pragma unroll
        for (int t = 0; t < 4; t++, q += 256) {
            int r = q >> 5, c4 = (q & 31) * 4;
            float4 m = *(float4*)&smem[N2F_OUT + r * 132 + c4];
            size_t gi = (size_t)(r0 + r) * DD + nc + c4;
            float4 n4 = __ldg((const float4*)&nodes[gi]);
            float4 b4 = __ldg((const float4*)&nb2[nc + c4]);
            *(float4*)&out_nodes[gi] = make_float4(n4.x + m.x + b4.x, n4.y + m.y + b4.y,
                                                   n4.z + m.z + b4.z, n4.w + m.w + b4.w);
        }
    }
}

// ============================================================
// Kernel 4: fp16 fused edge path; raw-fragment GEMM1 + coalesced
// NI/NJ/stats pass.  cp.async W staging.  2 CTAs/SM.
// ============================================================
#define F_NI   0
#define F_MU   512
#define F_RS   576
#define F_OUT  768                   // aliases H_E/H_W0 (dead at epilogue)
#define H_E    1536                  // half idx: [64][72]
#define H_W0   (H_E + 64 * 72)       // [64][72]
#define H_W1   (H_W0 + 64 * 72)      // [64][72]
#define H_HE   (H_W1 + 64 * 72)      // [64][520]
#define EDGE_SMEM_BYTES ((H_HE + 64 * 520) * 2)

__global__ __launch_bounds__(256, 2) void k_edge_mma(
    const float* __restrict__ edges,
    const float* __restrict__ eg,
    const float* __restrict__ ebt,
    const float* __restrict__ eb2,
    float* __restrict__ out_edges)
{
    extern __shared__ float smem[];
    __half* sh = (__half*)smem;
    const uint32_t sb = (uint32_t)__cvta_generic_to_shared(smem);
    const int tid = threadIdx.x;
    const int w = tid >> 5, lane = tid & 31;
    const int g = lane >> 2, tig = lane & 3;
    const int mt = (w & 3) * 16, ntw = (w >> 2) * 32;
    const int b = blockIdx.z, i = blockIdx.y;
    const int j0 = blockIdx.x * JT;

    const int arow = lane & 15, ak8 = (lane >> 4) << 3;
    const int bn = (lane & 7) + ((lane >> 4) << 3);
    const int bk8 = ((lane >> 3) & 1) << 3;

    const __half* njb = g_NJh + (size_t)((size_t)b * NN + j0) * HH;

    // ---- stage E [64][72] fp16 ----
    const float* etile = edges + ((size_t)((size_t)b * NN + i) * NN + j0) * EE;
    #pragma unroll
    for (int t = 0; t < 4; t++) {
        int q = t * 256 + tid;
        int j = q >> 4, k0 = (q & 15) * 4;
        float4 v = __ldg((const float4*)&etile[j * EE + k0]);
        *(uint2*)&sh[H_E + j * 72 + k0] = make_uint2(pack2(v.x, v.y), pack2(v.z, v.w));
    }
    // ---- NI cache ----
    const float* nip = g_NI + (size_t)((size_t)b * NN + i) * HH;
    smem[F_NI + tid] = __ldg(&nip[tid]);
    smem[F_NI + 256 + tid] = __ldg(&nip[256 + tid]);

    // issue W1 ch0 -> H_W0
    #pragma unroll
    for (int t = 0; t < 2; t++) {
        int q = t * 256 + tid;
        int n = q >> 3, k8 = (q & 7) * 8;
        cp16(sb + 2 * (H_W0 + n * 72 + k8), g_w1h + n * 64 + k8);
    }
    CP_COMMIT();
    __syncthreads();                           // E + NI visible

    // ---- hoist E fragments ----
    uint32_t ef[4][4];
    #pragma unroll
    for (int ks = 0; ks < 4; ks++)
        ldm_x4(ef[ks][0], ef[ks][1], ef[ks][2], ef[ks][3],
               sb + 2 * (H_E + (mt + arow) * 72 + ks * 16 + ak8));

    // ================= GEMM1: raw he = E@We -> sHe =========================
    for (int ch = 0; ch < 8; ch++) {
        CP_WAIT0();
        __syncthreads();                       // W_ch visible; prev consume done
        if (ch < 7) {
            const int wb = ((ch + 1) & 1) ? H_W1 : H_W0;
            #pragma unroll
            for (int t = 0; t < 2; t++) {
                int q = t * 256 + tid;
                int n = q >> 3, k8 = (q & 7) * 8;
                cp16(sb + 2 * (wb + n * 72 + k8), g_w1h + (ch + 1) * 4096 + n * 64 + k8);
            }
            CP_COMMIT();
        }
        const int bufo = (ch & 1) ? H_W1 : H_W0;
        float c[4][4];
        #pragma unroll
        for (int nj = 0; nj < 4; nj++)
            #pragma unroll
            for (int x = 0; x < 4; x++) c[nj][x] = 0.f;
        #pragma unroll
        for (int ks = 0; ks < 4; ks++) {
            int k0 = ks * 16;
            uint32_t p0, p1, p2, p3, q0, q1, q2, q3;
            ldm_x4(p0, p1, p2, p3, sb + 2 * (bufo + (ntw + bn) * 72 + k0 + bk8));
            ldm_x4(q0, q1, q2, q3, sb + 2 * (bufo + (ntw + 16 + bn) * 72 + k0 + bk8));
            mma_f16(c[0], ef[ks][0], ef[ks][1], ef[ks][2], ef[ks][3], p0, p1);
            mma_f16(c[1], ef[ks][0], ef[ks][1], ef[ks][2], ef[ks][3], p2, p3);
            mma_f16(c[2], ef[ks][0], ef[ks][1], ef[ks][2], ef[ks][3], q0, q1);
            mma_f16(c[3], ef[ks][0], ef[ks][1], ef[ks][2], ef[ks][3], q2, q3);
        }
        // raw fragment store only
        #pragma unroll
        for (int nj = 0; nj < 4; nj++) {
            int cl = ntw + nj * 8 + 2 * tig;
            #pragma unroll
            for (int rr = 0; rr < 2; rr++) {
                int row = mt + g + rr * 8;
                *(uint32_t*)&sh[H_HE + row * 520 + ch * 64 + cl] =
                    pack2(c[nj][rr * 2 + 0], c[nj][rr * 2 + 1]);
            }
        }
    }
    __syncthreads();                           // all raw he visible

    // issue W2 chunk0 early (overlaps pass1 + LN pass)
    #pragma unroll
    for (int t = 0; t < 2; t++) {
        int q = t * 256 + tid;
        int n = q >> 3, k8 = (q & 7) * 8;
        cp16(sb + 2 * (H_W0 + n * 72 + k8), g_w2h + n * 64 + k8);
    }
    CP_COMMIT();

    // ---- pass1: += NI + NJ (coalesced), stats in-lane ----
    {
        const int prow = tid >> 2;             // 0..63
        const int pcb = (tid & 3) * 128;       // 128-col strip
        const __half* njr = njb + (size_t)prow * HH + pcb;
        float s = 0.f, q2 = 0.f;
        #pragma unroll
        for (int t = 0; t < 16; t++) {
            int c0 = pcb + t * 8;
            uint4 m4 = *(uint4*)&sh[H_HE + prow * 520 + c0];
            uint4 n4 = __ldg((const uint4*)&njr[t * 8]);
            float4 ni0 = *(float4*)&smem[F_NI + c0];
            float4 ni1 = *(float4*)&smem[F_NI + c0 + 4];
            float2 a, nv;
            a = h2f(m4.x); nv = h2f(n4.x);
            float v0 = a.x + ni0.x + nv.x, v1 = a.y + ni0.y + nv.y;
            a = h2f(m4.y); nv = h2f(n4.y);
            float v2 = a.x + ni0.z + nv.x, v3 = a.y + ni0.w + nv.y;
            a = h2f(m4.z); nv = h2f(n4.z);
            float v4 = a.x + ni1.x + nv.x, v5 = a.y + ni1.y + nv.y;
            a = h2f(m4.w); nv = h2f(n4.w);
            float v6 = a.x + ni1.z + nv.x, v7 = a.y + ni1.w + nv.y;
            s  += v0 + v1 + v2 + v3 + v4 + v5 + v6 + v7;
            q2 += v0*v0 + v1*v1 + v2*v2 + v3*v3 + v4*v4 + v5*v5 + v6*v6 + v7*v7;
            m4.x = pack2(v0, v1); m4.y = pack2(v2, v3);
            m4.z = pack2(v4, v5); m4.w = pack2(v6, v7);
            *(uint4*)&sh[H_HE + prow * 520 + c0] = m4;
        }
        s  += __shfl_xor_sync(0xffffffffu, s, 1);
        s  += __shfl_xor_sync(0xffffffffu, s, 2);
        q2 += __shfl_xor_sync(0xffffffffu, q2, 1);
        q2 += __shfl_xor_sync(0xffffffffu, q2, 2);
        if ((tid & 3) == 0) {
            float mu = s * (1.f / HH);
            float var = q2 * (1.f / HH) - mu * mu;
            smem[F_MU + prow] = mu;
            smem[F_RS + prow] = rsqrtf(var + 1e-5f);
        }
    }
    __syncthreads();                           // he' + mu/rs visible

    // ---- coalesced in-place LN + relu pass ----
    {
        int wr = w * 8;
        #pragma unroll
        for (int pass = 0; pass < 2; pass++) {
            int cb = pass * 256 + lane * 8;
            float4 g0 = __ldg((const float4*)&eg[cb]);
            float4 g1 = __ldg((const float4*)&eg[cb + 4]);
            float4 t0 = __ldg((const float4*)&ebt[cb]);
            float4 t1 = __ldg((const float4*)&ebt[cb + 4]);
            #pragma unroll
            for (int r = 0; r < 8; r++) {
                int row = wr + r;
                float mu = smem[F_MU + row], rs = smem[F_RS + row];
                uint4 u = *(uint4*)&sh[H_HE + row * 520 + cb];
                float2 v;
                v = h2f(u.x);
                u.x = pack2(fmaxf((v.x - mu) * rs * g0.x + t0.x, 0.f),
                            fmaxf((v.y - mu) * rs * g0.y + t0.y, 0.f));
                v = h2f(u.y);
                u.y = pack2(fmaxf((v.x - mu) * rs * g0.z + t0.z, 0.f),
                            fmaxf((v.y - mu) * rs * g0.w + t0.w, 0.f));
                v = h2f(u.z);
                u.z = pack2(fmaxf((v.x - mu) * rs * g1.x + t1.x, 0.f),
                            fmaxf((v.y - mu) * rs * g1.y + t1.y, 0.f));
                v = h2f(u.w);
                u.w = pack2(fmaxf((v.x - mu) * rs * g1.z + t1.z, 0.f),
                            fmaxf((v.y - mu) * rs * g1.w + t1.w, 0.f));
                *(uint4*)&sh[H_HE + row * 520 + cb] = u;
            }
        }
    }

    // ================= GEMM2: out = ln_relu_he @ ew2 =======================
    float c2[4][4];
    #pragma unroll
    for (int nj = 0; nj < 4; nj++)
        #pragma unroll
        for (int x = 0; x < 4; x++) c2[nj][x] = 0.f;

    for (int kc = 0; kc < 8; kc++) {
        CP_WAIT0();
        __syncthreads();
        if (kc < 7) {
            const int wb = ((kc + 1) & 1) ? H_W1 : H_W0;
            #pragma unroll
            for (int t = 0; t < 2; t++) {
                int q = t * 256 + tid;
                int n = q >> 3, k8 = (q & 7) * 8;
                cp16(sb + 2 * (wb + n * 72 + k8), g_w2h + (kc + 1) * 4096 + n * 64 + k8);
            }
            CP_COMMIT();
        }
        const int bufo = (kc & 1) ? H_W1 : H_W0;
        #pragma unroll
        for (int ks = 0; ks < 4; ks++) {
            int k0 = ks * 16;
            uint32_t a0, a1, a2, a3, p0, p1, p2, p3, q0, q1, q2, q3;
            ldm_x4(a0, a1, a2, a3,
                   sb + 2 * (H_HE + (mt + arow) * 520 + kc * 64 + k0 + ak8));
            ldm_x4(p0, p1, p2, p3, sb + 2 * (bufo + (ntw + bn) * 72 + k0 + bk8));
            ldm_x4(q0, q1, q2, q3, sb + 2 * (bufo + (ntw + 16 + bn) * 72 + k0 + bk8));
            mma_f16(c2[0], a0, a1, a2, a3, p0, p1);
            mma_f16(c2[1], a0, a1, a2, a3, p2, p3);
            mma_f16(c2[2], a0, a1, a2, a3, q0, q1);
            mma_f16(c2[3], a0, a1, a2, a3, q2, q3);
        }
    }
    __syncthreads();

    // ---- epilogue: bounce via smem, coalesced residual + store ----
    #pragma unroll
    for (int nj = 0; nj < 4; nj++) {
        int cl = ntw + nj * 8 + 2 * tig;
        #pragma unroll
        for (int rr = 0; rr < 2; rr++) {
            int row = mt + g + rr * 8;
            *(float2*)&smem[F_OUT + row * 68 + cl] =
                make_float2(c2[nj][rr * 2 + 0], c2[nj][rr * 2 + 1]);
        }
    }
    __syncthreads();
    #pragma unroll
    for (int t = 0; t < 4; t++) {
        int q = t * 256 + tid;
        int r = q >> 4, c4 = (q & 15) * 4;
        float4 m = *(float4*)&smem[F_OUT + r * 68 + c4];
        size_t gbase = ((size_t)((size_t)b * NN + i) * NN + j0 + r) * EE + c4;
        float4 e4 = __ldg((const float4*)&edges[gbase]);
        float4 b4 = __ldg((const float4*)&eb2[c4]);
        float4 o = make_float4(e4.x + m.x + b4.x, e4.y + m.y + b4.y,
                               e4.z + m.z + b4.z, e4.w + m.w + b4.w);
        *(float4*)&out_edges[gbase] = o;
    }
}

// ============================================================
extern "C" void kernel_launch(void* const* d_in, const int* in_sizes, int n_in,
                              void* d_out, int out_size)
{
    const float* nodes = (const float*)d_in[0];
    const float* edges = (const float*)d_in[1];
    const float* adj   = (const float*)d_in[2];
    const float* nw1   = (const float*)d_in[3];
    const float* nb1   = (const float*)d_in[4];
    const float* ng    = (const float*)d_in[5];
    const float* nbt   = (const float*)d_in[6];
    const float* nw2   = (const float*)d_in[7];
    const float* nb2   = (const float*)d_in[8];
    const float* ew1   = (const float*)d_in[9];
    const float* eb1   = (const float*)d_in[10];
    const float* eg    = (const float*)d_in[11];
    const float* ebt   = (const float*)d_in[12];
    const float* ew2   = (const float*)d_in[13];
    const float* eb2   = (const float*)d_in[14];

    float* out_nodes = (float*)d_out;
    float* out_edges = out_nodes + (size_t)BB * NN * DD;

    cudaFuncSetAttribute(k_edge_mma, cudaFuncAttributeMaxDynamicSharedMemorySize,
                         EDGE_SMEM_BYTES);
    cudaFuncSetAttribute(k_ninj_mma, cudaFuncAttributeMaxDynamicSharedMemorySize,
                         NINJ_SMEM_BYTES);
    cudaFuncSetAttribute(k_node1, cudaFuncAttributeMaxDynamicSharedMemorySize,
                         N1_SMEM_BYTES);
    cudaFuncSetAttribute(k_node2, cudaFuncAttributeMaxDynamicSharedMemorySize,
                         N2_SMEM_BYTES);

    static cudaStream_t s2 = nullptr;
    static cudaEvent_t evFork = nullptr, evJoin = nullptr;
    if (s2 == nullptr) {
        if (cudaStreamCreateWithFlags(&s2, cudaStreamNonBlocking) != cudaSuccess)
            s2 = nullptr;
        if (s2) {
            cudaEventCreateWithFlags(&evFork, cudaEventDisableTiming);
            cudaEventCreateWithFlags(&evJoin, cudaEventDisableTiming);
        }
    }

    if (s2) {
        cudaEventRecord(evFork, 0);
        cudaStreamWaitEvent(s2, evFork, 0);
        k_node1<<<48, 256, N1_SMEM_BYTES, s2>>>(nodes, edges, adj, nw1, nb1, ng, nbt);
        k_node2<<<dim3(6, 24), 256, N2_SMEM_BYTES, s2>>>(nodes, nw2, nb2, out_nodes);
        cudaEventRecord(evJoin, s2);
        k_prep<<<296, 256>>>(ew1, ew2);
        k_ninj_mma<<<dim3(8, 24), 256, NINJ_SMEM_BYTES>>>(nodes, eb1);
        k_edge_mma<<<dim3(NN / JT, NN, BB), 256, EDGE_SMEM_BYTES>>>(edges, eg, ebt, eb2, out_edges);
        cudaStreamWaitEvent(0, evJoin, 0);
    } else {
        k_prep<<<296, 256>>>(ew1, ew2);
        k_ninj_mma<<<dim3(8, 24), 256, NINJ_SMEM_BYTES>>>(nodes, eb1);
        k_node1<<<48, 256, N1_SMEM_BYTES>>>(nodes, edges, adj, nw1, nb1, ng, nbt);
        k_node2<<<dim3(6, 24), 256, N2_SMEM_BYTES>>>(nodes, nw2, nb2, out_nodes);
        k_edge_mma<<<dim3(NN / JT, NN, BB), 256, EDGE_SMEM_BYTES>>>(edges, eg, ebt, eb2, out_edges);
    }
}

// round 15
// speedup vs baseline: 1.4090x; 1.4090x over previous
#include <cuda_runtime.h>
#include <cuda_fp16.h>
#include <cstdint>

#define BB 2
#define NN 384
#define DD 768
#define EE 64
#define HH 512
#define JT 64

// -------- scratch (no allocations allowed) --------
__device__ float  g_NI [BB * NN * HH];       // 1.5 MB
__device__ __half g_NJh[BB * NN * HH];       // 768 KB
__device__ __half g_heh[BB * NN * HH];       // 768 KB
__device__ __half g_w1h[8 * 64 * 64];        // We  chunks [ch][n][k]
__device__ __half g_w2h[8 * 64 * 64];        // ew2 chunks [kc][n][k]
__device__ __half g_wijh[2 * 512 * 768];     // Wi/Wj transposed [z][n][k]

__device__ __forceinline__ uint32_t pack2(float a, float b) {
    __half2 h = __floats2half2_rn(a, b);
    return *reinterpret_cast<uint32_t*>(&h);
}
__device__ __forceinline__ float2 h2f(uint32_t u) {
    return __half22float2(*reinterpret_cast<__half2*>(&u));
}
__device__ __forceinline__ void ldm_x4(uint32_t& r0, uint32_t& r1,
                                       uint32_t& r2, uint32_t& r3, uint32_t addr) {
    asm volatile("ldmatrix.sync.aligned.m8n8.x4.shared.b16 {%0,%1,%2,%3}, [%4];"
                 : "=r"(r0), "=r"(r1), "=r"(r2), "=r"(r3) : "r"(addr));
}
__device__ __forceinline__ void mma_f16(float c[4],
                                        uint32_t a0, uint32_t a1, uint32_t a2, uint32_t a3,
                                        uint32_t b0, uint32_t b1) {
    asm volatile("mma.sync.aligned.m16n8k16.row.col.f32.f16.f16.f32 "
        "{%0,%1,%2,%3}, {%4,%5,%6,%7}, {%8,%9}, {%0,%1,%2,%3};"
        : "+f"(c[0]), "+f"(c[1]), "+f"(c[2]), "+f"(c[3])
        : "r"(a0), "r"(a1), "r"(a2), "r"(a3), "r"(b0), "r"(b1));
}
__device__ __forceinline__ void cp16(uint32_t dst, const void* src) {
    asm volatile("cp.async.cg.shared.global [%0], [%1], 16;" :: "r"(dst), "l"(src));
}
#define CP_COMMIT() asm volatile("cp.async.commit_group;" ::: "memory")
#define CP_WAIT0()  asm volatile("cp.async.wait_group 0;" ::: "memory")

// warp-tile m16 x n32 GEMM over one k=64 chunk; B stride 72 halves
__device__ __forceinline__ void gemm_16x32(uint32_t sb, int offA, int strideA, int colA,
                                           int offB, int mt, int nt, int lane,
                                           float c[4][4]) {
    const int arow = lane & 15, ak8 = (lane >> 4) << 3;
    const int bn = (lane & 7) + ((lane >> 4) << 3);
    const int bk8 = ((lane >> 3) & 1) << 3;
    #pragma unroll
    for (int ks = 0; ks < 4; ks++) {
        int k0 = ks * 16;
        uint32_t a0, a1, a2, a3, p0, p1, p2, p3, q0, q1, q2, q3;
        ldm_x4(a0, a1, a2, a3, sb + 2 * (offA + (mt + arow) * strideA + colA + k0 + ak8));
        ldm_x4(p0, p1, p2, p3, sb + 2 * (offB + (nt + bn) * 72 + k0 + bk8));
        ldm_x4(q0, q1, q2, q3, sb + 2 * (offB + (nt + 16 + bn) * 72 + k0 + bk8));
        mma_f16(c[0], a0, a1, a2, a3, p0, p1);
        mma_f16(c[1], a0, a1, a2, a3, p2, p3);
        mma_f16(c[2], a0, a1, a2, a3, q0, q1);
        mma_f16(c[3], a0, a1, a2, a3, q2, q3);
    }
}

// ============================================================
// Kernel 0: weight pre-conversion to fp16 staging layouts
// ============================================================
__global__ __launch_bounds__(256) void k_prep(const float* __restrict__ ew1,
                                              const float* __restrict__ ew2)
{
    int idx = blockIdx.x * 256 + threadIdx.x;
    int stride = gridDim.x * 256;
    for (int i = idx; i < 8 * 64 * 64; i += stride) {
        int ch = i >> 12, r = i & 4095, n = r >> 6, k = r & 63;
        g_w1h[i] = __float2half_rn(ew1[(size_t)k * HH + ch * 64 + n]);
    }
    for (int i = idx; i < 8 * 64 * 64; i += stride) {
        int kc = i >> 12, r = i & 4095, n = r >> 6, k = r & 63;
        g_w2h[i] = __float2half_rn(ew2[(size_t)(kc * 64 + k) * EE + n]);
    }
    for (int i = idx; i < 2 * 512 * 768; i += stride) {
        int z = i / (512 * 768), r = i % (512 * 768), n = r / 768, k = r % 768;
        g_wijh[i] = __float2half_rn(ew1[(size_t)(EE + z * DD + k) * HH + n]);
    }
}

// ============================================================
// Kernel 1: NI = nodes@Wi + eb1 (fp32 out); NJ = nodes@Wj (fp16 out)
// 32-row tiles, grid (8, 24) = 192 CTAs.  (verified R12 version)
// ============================================================
#define NJ_A0 0
#define NJ_A1 (32 * 72)
#define NJ_B0 (2 * 32 * 72)
#define NJ_B1 (NJ_B0 + 128 * 72)
#define NINJ_SMEM_BYTES ((NJ_B1 + 128 * 72) * 2)

__global__ __launch_bounds__(256) void k_ninj_mma(const float* __restrict__ nodes,
                                                  const float* __restrict__ eb1)
{
    extern __shared__ __half shn[];
    const uint32_t sb = (uint32_t)__cvta_generic_to_shared(shn);
    const int tid = threadIdx.x;
    const int w = tid >> 5, lane = tid & 31;
    const int g = lane >> 2, tig = lane & 3;
    const int mt = (w & 1) * 16, ntb = (w >> 1) * 32;
    const int gc = blockIdx.x * 128;
    const int r0 = blockIdx.y * 32;
    const bool is_ni = (gc < HH);
    const int z = is_ni ? 0 : 1;
    const int col0 = is_ni ? gc : (gc - HH);
    const __half* wsrc = g_wijh + (size_t)z * 512 * 768;

    float cacc[4][4];
    #pragma unroll
    for (int nj = 0; nj < 4; nj++)
        #pragma unroll
        for (int x = 0; x < 4; x++) cacc[nj][x] = 0.f;

    uint2 areg[2];
    #pragma unroll
    for (int t = 0; t < 2; t++) {
        int q = t * 256 + tid;
        int r = q >> 4, k0 = (q & 15) * 4;
        float4 v = __ldg((const float4*)&nodes[(size_t)(r0 + r) * DD + k0]);
        areg[t] = make_uint2(pack2(v.x, v.y), pack2(v.z, v.w));
    }
    #pragma unroll
    for (int t = 0; t < 4; t++) {
        int q = t * 256 + tid;
        int n = q >> 3, k8 = (q & 7) * 8;
        cp16(sb + 2 * (NJ_B0 + n * 72 + k8), wsrc + (size_t)(col0 + n) * 768 + k8);
    }
    CP_COMMIT();

    for (int kc = 0; kc < 12; kc++) {
        const int abuf = (kc & 1) ? NJ_A1 : NJ_A0;
        #pragma unroll
        for (int t = 0; t < 2; t++) {
            int q = t * 256 + tid;
            int r = q >> 4, k0 = (q & 15) * 4;
            *(uint2*)&shn[abuf + r * 72 + k0] = areg[t];
        }
        if (kc < 11) {
            #pragma unroll
            for (int t = 0; t < 2; t++) {
                int q = t * 256 + tid;
                int r = q >> 4, k0 = (q & 15) * 4;
                float4 v = __ldg((const float4*)&nodes[(size_t)(r0 + r) * DD + (kc + 1) * 64 + k0]);
                areg[t] = make_uint2(pack2(v.x, v.y), pack2(v.z, v.w));
            }
        }
        CP_WAIT0();
        __syncthreads();
        if (kc < 11) {
            const int nb = (kc & 1) ? NJ_B0 : NJ_B1;
            #pragma unroll
            for (int t = 0; t < 4; t++) {
                int q = t * 256 + tid;
                int n = q >> 3, k8 = (q & 7) * 8;
                cp16(sb + 2 * (nb + n * 72 + k8),
                     wsrc + (size_t)(col0 + n) * 768 + (kc + 1) * 64 + k8);
            }
            CP_COMMIT();
        }
        const int bbuf = (kc & 1) ? NJ_B1 : NJ_B0;
        gemm_16x32(sb, abuf, 72, 0, bbuf, mt, ntb, lane, cacc);
        __syncthreads();
    }

    #pragma unroll
    for (int nj = 0; nj < 4; nj++) {
        int coll = ntb + nj * 8 + 2 * tig;
        #pragma unroll
        for (int rr = 0; rr < 2; rr++) {
            int row = mt + g + rr * 8;
            float v0 = cacc[nj][rr * 2 + 0];
            float v1 = cacc[nj][rr * 2 + 1];
            if (is_ni) {
                float2 e = __ldg((const float2*)&eb1[gc + coll]);
                *(float2*)&g_NI[(size_t)(r0 + row) * HH + gc + coll] =
                    make_float2(v0 + e.x, v1 + e.y);
            } else {
                *(uint32_t*)&g_NJh[(size_t)(r0 + row) * HH + col0 + coll] = pack2(v0, v1);
            }
        }
    }
}

// ============================================================
// Kernel 2: node path part 1 (unchanged)
// ============================================================
#define N1_SUM 0
#define N1_SQ  16
#define N1_MU  32
#define N1_RS  48
#define N1_AGG 64
#define N1H_A  2176
#define N1H_B  (N1H_A + 16 * 72)
#define N1_SMEM_BYTES ((N1H_B + 512 * 72) * 2)

__global__ __launch_bounds__(256) void k_node1(
    const float* __restrict__ nodes, const float* __restrict__ edges,
    const float* __restrict__ adj, const float* __restrict__ nw1,
    const float* __restrict__ nb1, const float* __restrict__ ng,
    const float* __restrict__ nbt)
{
    extern __shared__ float smem[];
    __half* sh = (__half*)smem;
    const uint32_t sb = (uint32_t)__cvta_generic_to_shared(smem);
    const int tid = threadIdx.x;
    const int w = tid >> 5, lane = tid & 31;
    const int g = lane >> 2, tig = lane & 3;
    const int r0 = blockIdx.x * 16;
    const int b = r0 / NN, i0 = r0 % NN;

    if (tid < 16) { smem[N1_SUM + tid] = 0.f; smem[N1_SQ + tid] = 0.f; }

    {
        int r = tid >> 4, e4 = (tid & 15) * 4;
        const float* er = edges + (size_t)((size_t)(b * NN + i0 + r) * NN) * EE;
        const float* ar = adj + (size_t)(b * NN + i0 + r) * NN;
        float4 acc = make_float4(0.f, 0.f, 0.f, 0.f);
        for (int j = 0; j < NN; j += 4) {
            float a0 = ar[j], a1 = ar[j + 1], a2 = ar[j + 2], a3 = ar[j + 3];
            if (a0 != 0.f) { float4 v = __ldg((const float4*)&er[(size_t)j * EE + e4]);
                acc.x += v.x * a0; acc.y += v.y * a0; acc.z += v.z * a0; acc.w += v.w * a0; }
            if (a1 != 0.f) { float4 v = __ldg((const float4*)&er[(size_t)(j + 1) * EE + e4]);
                acc.x += v.x * a1; acc.y += v.y * a1; acc.z += v.z * a1; acc.w += v.w * a1; }
            if (a2 != 0.f) { float4 v = __ldg((const float4*)&er[(size_t)(j + 2) * EE + e4]);
                acc.x += v.x * a2; acc.y += v.y * a2; acc.z += v.z * a2; acc.w += v.w * a2; }
            if (a3 != 0.f) { float4 v = __ldg((const float4*)&er[(size_t)(j + 3) * EE + e4]);
                acc.x += v.x * a3; acc.y += v.y * a3; acc.z += v.z * a3; acc.w += v.w * a3; }
        }
        *(float4*)&smem[N1_AGG + r * 64 + e4] = acc;
    }
    __syncthreads();

    float cacc[2][4][4];
    #pragma unroll
    for (int s = 0; s < 2; s++)
        #pragma unroll
        for (int nj = 0; nj < 4; nj++)
            #pragma unroll
            for (int x = 0; x < 4; x++) cacc[s][nj][x] = 0.f;

    for (int kc = 0; kc < 13; kc++) {
        __syncthreads();
        {
            int r = tid >> 4, k0 = (tid & 15) * 4;
            float4 v;
            if (kc == 0) v = *(float4*)&smem[N1_AGG + r * 64 + k0];
            else {
                v = __ldg((const float4*)&nodes[(size_t)(r0 + r) * DD + (kc - 1) * 64 + k0]);
                v.x *= (float)NN; v.y *= (float)NN; v.z *= (float)NN; v.w *= (float)NN;
            }
            *(uint2*)&sh[N1H_A + r * 72 + k0] = make_uint2(pack2(v.x, v.y), pack2(v.z, v.w));
        }
        {
            int q = tid;
            for (int t = 0; t < 32; t++, q += 256) {
                int n = q & 511, k0 = (q >> 9) * 4;
                const float* p = nw1 + (size_t)(kc * 64 + k0) * HH + n;
                *(uint2*)&sh[N1H_B + n * 72 + k0] =
                    make_uint2(pack2(__ldg(p), __ldg(p + HH)),
                               pack2(__ldg(p + 2 * HH), __ldg(p + 3 * HH)));
            }
        }
        __syncthreads();
        gemm_16x32(sb, N1H_A, 72, 0, N1H_B, 0, w * 64, lane, cacc[0]);
        gemm_16x32(sb, N1H_A, 72, 0, N1H_B, 0, w * 64 + 32, lane, cacc[1]);
    }

    float rsum[2] = {0.f, 0.f}, rsq[2] = {0.f, 0.f};
    #pragma unroll
    for (int s = 0; s < 2; s++)
        #pragma unroll
        for (int nj = 0; nj < 4; nj++) {
            int coll = w * 64 + s * 32 + nj * 8 + 2 * tig;
            float2 b1 = __ldg((const float2*)&nb1[coll]);
            #pragma unroll
            for (int rr = 0; rr < 2; rr++) {
                float v0 = cacc[s][nj][rr * 2 + 0] + b1.x;
                float v1 = cacc[s][nj][rr * 2 + 1] + b1.y;
                cacc[s][nj][rr * 2 + 0] = v0;
                cacc[s][nj][rr * 2 + 1] = v1;
                rsum[rr] += v0 + v1;
                rsq[rr]  += v0 * v0 + v1 * v1;
            }
        }
    #pragma unroll
    for (int rr = 0; rr < 2; rr++) {
        float s = rsum[rr], q2 = rsq[rr];
        s  += __shfl_xor_sync(0xffffffffu, s, 1);
        s  += __shfl_xor_sync(0xffffffffu, s, 2);
        q2 += __shfl_xor_sync(0xffffffffu, q2, 1);
        q2 += __shfl_xor_sync(0xffffffffu, q2, 2);
        if (tig == 0) {
            atomicAdd(&smem[N1_SUM + g + rr * 8], s);
            atomicAdd(&smem[N1_SQ + g + rr * 8], q2);
        }
    }
    __syncthreads();
    if (tid < 16) {
        float mu = smem[N1_SUM + tid] * (1.f / HH);
        float var = smem[N1_SQ + tid] * (1.f / HH) - mu * mu;
        smem[N1_MU + tid] = mu;
        smem[N1_RS + tid] = rsqrtf(var + 1e-5f);
    }
    __syncthreads();
    const float mu0 = smem[N1_MU + g],     rs0 = smem[N1_RS + g];
    const float mu1 = smem[N1_MU + g + 8], rs1 = smem[N1_RS + g + 8];

    #pragma unroll
    for (int s = 0; s < 2; s++)
        #pragma unroll
        for (int nj = 0; nj < 4; nj++) {
            int coll = w * 64 + s * 32 + nj * 8 + 2 * tig;
            float2 gg = __ldg((const float2*)&ng[coll]);
            float2 bb = __ldg((const float2*)&nbt[coll]);
            float v0 = fmaxf((cacc[s][nj][0] - mu0) * rs0 * gg.x + bb.x, 0.f);
            float v1 = fmaxf((cacc[s][nj][1] - mu0) * rs0 * gg.y + bb.y, 0.f);
            float v2 = fmaxf((cacc[s][nj][2] - mu1) * rs1 * gg.x + bb.x, 0.f);
            float v3 = fmaxf((cacc[s][nj][3] - mu1) * rs1 * gg.y + bb.y, 0.f);
            *(uint32_t*)&sh[N1H_B + g * 520 + coll]       = pack2(v0, v1);
            *(uint32_t*)&sh[N1H_B + (g + 8) * 520 + coll] = pack2(v2, v3);
        }
    __syncthreads();
    {
        int q = tid;
        #pragma unroll
        for (int t = 0; t < 4; t++, q += 256) {
            int r = q >> 6, c0 = (q & 63) * 8;
            *(uint4*)&g_heh[(size_t)(r0 + r) * HH + c0] = *(uint4*)&sh[N1H_B + r * 520 + c0];
        }
    }
}

// ============================================================
// Kernel 3: node path part 2 (unchanged)
// ============================================================
#define N2H_HE 0
#define N2H_B  (32 * 520)
#define N2F_OUT 12928
#define N2_SMEM_BYTES ((N2F_OUT + 32 * 132) * 4)

__global__ __launch_bounds__(256) void k_node2(
    const float* __restrict__ nodes, const float* __restrict__ nw2,
    const float* __restrict__ nb2, float* __restrict__ out_nodes)
{
    extern __shared__ float smem[];
    __half* sh = (__half*)smem;
    const uint32_t sb = (uint32_t)__cvta_generic_to_shared(smem);
    const int tid = threadIdx.x;
    const int w = tid >> 5, lane = tid & 31;
    const int g = lane >> 2, tig = lane & 3;
    const int mt = (w & 1) * 16, nt = (w >> 1) * 32;
    const int nc = blockIdx.x * 128;
    const int r0 = blockIdx.y * 32;

    {
        int q = tid;
        #pragma unroll
        for (int t = 0; t < 8; t++, q += 256) {
            int r = q >> 6, c0 = (q & 63) * 8;
            *(uint4*)&sh[N2H_HE + r * 520 + c0] = *(const uint4*)&g_heh[(size_t)(r0 + r) * HH + c0];
        }
    }

    float c2[4][4];
    #pragma unroll
    for (int nj = 0; nj < 4; nj++)
        #pragma unroll
        for (int x = 0; x < 4; x++) c2[nj][x] = 0.f;

    for (int kc = 0; kc < 8; kc++) {
        __syncthreads();
        {
            int q = tid;
            #pragma unroll
            for (int t = 0; t < 8; t++, q += 256) {
                int n = q & 127, k0 = (q >> 7) * 4;
                const float* p = nw2 + (size_t)(kc * 64 + k0) * DD + nc + n;
                *(uint2*)&sh[N2H_B + n * 72 + k0] =
                    make_uint2(pack2(__ldg(p), __ldg(p + DD)),
                               pack2(__ldg(p + 2 * DD), __ldg(p + 3 * DD)));
            }
        }
        __syncthreads();
        gemm_16x32(sb, N2H_HE, 520, kc * 64, N2H_B, mt, nt, lane, c2);
    }

    __syncthreads();
    #pragma unroll
    for (int nj = 0; nj < 4; nj++) {
        int coll = nt + nj * 8 + 2 * tig;
        #pragma unroll
        for (int rr = 0; rr < 2; rr++) {
            int row = mt + g + rr * 8;
            *(float2*)&smem[N2F_OUT + row * 132 + coll] =
                make_float2(c2[nj][rr * 2 + 0], c2[nj][rr * 2 + 1]);
        }
    }
    __syncthreads();
    {
        int q = tid;
        #pragma unroll
        for (int t = 0; t < 4; t++, q += 256) {
            int r = q >> 5, c4 = (q & 31) * 4;
            float4 m = *(float4*)&smem[N2F_OUT + r * 132 + c4];
            size_t gi = (size_t)(r0 + r) * DD + nc + c4;
            float4 n4 = __ldg((const float4*)&nodes[gi]);
            float4 b4 = __ldg((const float4*)&nb2[nc + c4]);
            *(float4*)&out_nodes[gi] = make_float4(n4.x + m.x + b4.x, n4.y + m.y + b4.y,
                                                   n4.z + m.z + b4.z, n4.w + m.w + b4.w);
        }
    }
}

// ============================================================
// Kernel 4: fp16 fused edge path with cp.async staging (R11 version,
// proven 337 us total).  2 CTAs/SM.
// ============================================================
#define F_NI   0
#define F_SUM  512
#define F_SQ   576
#define F_MU   640
#define F_RS   704
#define F_OUT  768                   // aliases H_E + H_NJ0 (dead at epilogue)
#define H_E    1536                  // half idx: [64][72]; doubles as NJ buf1
#define H_NJ0  (H_E + 64 * 72)       // [64][72]
#define H_W0   (H_NJ0 + 64 * 72)     // [64][72]
#define H_W1   (H_W0 + 64 * 72)      // [64][72]
#define H_HE   (H_W1 + 64 * 72)      // [64][520]
#define EDGE_SMEM_BYTES ((H_HE + 64 * 520) * 2)

__global__ __launch_bounds__(256, 2) void k_edge_mma(
    const float* __restrict__ edges,
    const float* __restrict__ eg,
    const float* __restrict__ ebt,
    const float* __restrict__ eb2,
    float* __restrict__ out_edges)
{
    extern __shared__ float smem[];
    __half* sh = (__half*)smem;
    const uint32_t sb = (uint32_t)__cvta_generic_to_shared(smem);
    const int tid = threadIdx.x;
    const int w = tid >> 5, lane = tid & 31;
    const int g = lane >> 2, tig = lane & 3;
    const int mt = (w & 3) * 16, ntw = (w >> 2) * 32;
    const int b = blockIdx.z, i = blockIdx.y;
    const int j0 = blockIdx.x * JT;

    const int arow = lane & 15, ak8 = (lane >> 4) << 3;
    const int bn = (lane & 7) + ((lane >> 4) << 3);
    const int bk8 = ((lane >> 3) & 1) << 3;

    const __half* njb = g_NJh + (size_t)((size_t)b * NN + j0) * HH;

    // ---- stage E [64][72] fp16 (fp32 src needs cvt) ----
    const float* etile = edges + ((size_t)((size_t)b * NN + i) * NN + j0) * EE;
    #pragma unroll
    for (int t = 0; t < 4; t++) {
        int q = t * 256 + tid;
        int j = q >> 4, k0 = (q & 15) * 4;
        float4 v = __ldg((const float4*)&etile[j * EE + k0]);
        *(uint2*)&sh[H_E + j * 72 + k0] = make_uint2(pack2(v.x, v.y), pack2(v.z, v.w));
    }
    // ---- NI cache + zero stats ----
    const float* nip = g_NI + (size_t)((size_t)b * NN + i) * HH;
    smem[F_NI + tid] = __ldg(&nip[tid]);
    smem[F_NI + 256 + tid] = __ldg(&nip[256 + tid]);
    if (tid < 64) { smem[F_SUM + tid] = 0.f; smem[F_SQ + tid] = 0.f; }

    // issue group 0: W1 ch0 -> H_W0, NJ ch0 -> H_NJ0
    {
        #pragma unroll
        for (int t = 0; t < 2; t++) {
            int q = t * 256 + tid;             // 512 segs each
            int n = q >> 3, k8 = (q & 7) * 8;
            cp16(sb + 2 * (H_W0 + n * 72 + k8), g_w1h + n * 64 + k8);
            cp16(sb + 2 * (H_NJ0 + n * 72 + k8), njb + (size_t)n * HH + k8);
        }
        CP_COMMIT();
    }
    __syncthreads();                           // E + NI visible

    // ---- hoist E fragments ----
    uint32_t ef[4][4];
    #pragma unroll
    for (int ks = 0; ks < 4; ks++)
        ldm_x4(ef[ks][0], ef[ks][1], ef[ks][2], ef[ks][3],
               sb + 2 * (H_E + (mt + arow) * 72 + ks * 16 + ak8));

    // ================= GEMM1: he = E@We + NI + NJ ==========================
    float rsum[2] = {0.f, 0.f}, rsq[2] = {0.f, 0.f};
    for (int ch = 0; ch < 8; ch++) {
        CP_WAIT0();
        __syncthreads();                       // group ch visible; prev consume done
        if (ch < 7) {
            const int wb = ((ch + 1) & 1) ? H_W1 : H_W0;
            const int nb = ((ch + 1) & 1) ? H_E : H_NJ0;   // buf1 = dead E tile
            #pragma unroll
            for (int t = 0; t < 2; t++) {
                int q = t * 256 + tid;
                int n = q >> 3, k8 = (q & 7) * 8;
                cp16(sb + 2 * (wb + n * 72 + k8), g_w1h + (ch + 1) * 4096 + n * 64 + k8);
                cp16(sb + 2 * (nb + n * 72 + k8), njb + (size_t)n * HH + (ch + 1) * 64 + k8);
            }
            CP_COMMIT();
        }
        const int bufo = (ch & 1) ? H_W1 : H_W0;
        const int njbf = (ch & 1) ? H_E : H_NJ0;
        float c[4][4];
        #pragma unroll
        for (int nj = 0; nj < 4; nj++)
            #pragma unroll
            for (int x = 0; x < 4; x++) c[nj][x] = 0.f;
        #pragma unroll
        for (int ks = 0; ks < 4; ks++) {
            int k0 = ks * 16;
            uint32_t p0, p1, p2, p3, q0, q1, q2, q3;
            ldm_x4(p0, p1, p2, p3, sb + 2 * (bufo + (ntw + bn) * 72 + k0 + bk8));
            ldm_x4(q0, q1, q2, q3, sb + 2 * (bufo + (ntw + 16 + bn) * 72 + k0 + bk8));
            mma_f16(c[0], ef[ks][0], ef[ks][1], ef[ks][2], ef[ks][3], p0, p1);
            mma_f16(c[1], ef[ks][0], ef[ks][1], ef[ks][2], ef[ks][3], p2, p3);
            mma_f16(c[2], ef[ks][0], ef[ks][1], ef[ks][2], ef[ks][3], q0, q1);
            mma_f16(c[3], ef[ks][0], ef[ks][1], ef[ks][2], ef[ks][3], q2, q3);
        }
        #pragma unroll
        for (int nj = 0; nj < 4; nj++) {
            int cl = ntw + nj * 8 + 2 * tig;
            float2 ni = *(float2*)&smem[F_NI + ch * 64 + cl];
            #pragma unroll
            for (int rr = 0; rr < 2; rr++) {
                int row = mt + g + rr * 8;
                float2 njv = h2f(*(uint32_t*)&sh[njbf + row * 72 + cl]);
                float v0 = c[nj][rr * 2 + 0] + ni.x + njv.x;
                float v1 = c[nj][rr * 2 + 1] + ni.y + njv.y;
                rsum[rr] += v0 + v1;
                rsq[rr]  += v0 * v0 + v1 * v1;
                *(uint32_t*)&sh[H_HE + row * 520 + ch * 64 + cl] = pack2(v0, v1);
            }
        }
    }
    __syncthreads();                           // last consume done

    // issue W2 chunk0 early (overlaps stats + LN pass)
    #pragma unroll
    for (int t = 0; t < 2; t++) {
        int q = t * 256 + tid;
        int n = q >> 3, k8 = (q & 7) * 8;
        cp16(sb + 2 * (H_W0 + n * 72 + k8), g_w2h + n * 64 + k8);
    }
    CP_COMMIT();

    // ---- LN stats reduction ----
    #pragma unroll
    for (int rr = 0; rr < 2; rr++) {
        float s = rsum[rr], q2 = rsq[rr];
        s  += __shfl_xor_sync(0xffffffffu, s, 1);
        s  += __shfl_xor_sync(0xffffffffu, s, 2);
        q2 += __shfl_xor_sync(0xffffffffu, q2, 1);
        q2 += __shfl_xor_sync(0xffffffffu, q2, 2);
        if (tig == 0) {
            atomicAdd(&smem[F_SUM + mt + g + rr * 8], s);
            atomicAdd(&smem[F_SQ  + mt + g + rr * 8], q2);
        }
    }
    __syncthreads();
    if (tid < 64) {
        float mu = smem[F_SUM + tid] * (1.f / HH);
        float var = smem[F_SQ + tid] * (1.f / HH) - mu * mu;
        smem[F_MU + tid] = mu;
        smem[F_RS + tid] = rsqrtf(var + 1e-5f);
    }
    __syncthreads();

    // ---- coalesced in-place LN + relu pass over he ----
    {
        int wr = w * 8;
        #pragma unroll
        for (int pass = 0; pass < 2; pass++) {
            int cb = pass * 256 + lane * 8;
            float4 g0 = __ldg((const float4*)&eg[cb]);
            float4 g1 = __ldg((const float4*)&eg[cb + 4]);
            float4 t0 = __ldg((const float4*)&ebt[cb]);
            float4 t1 = __ldg((const float4*)&ebt[cb + 4]);
            #pragma unroll
            for (int r = 0; r < 8; r++) {
                int row = wr + r;
                float mu = smem[F_MU + row], rs = smem[F_RS + row];
                uint4 u = *(uint4*)&sh[H_HE + row * 520 + cb];
                float2 v;
                v = h2f(u.x);
                u.x = pack2(fmaxf((v.x - mu) * rs * g0.x + t0.x, 0.f),
                            fmaxf((v.y - mu) * rs * g0.y + t0.y, 0.f));
                v = h2f(u.y);
                u.y = pack2(fmaxf((v.x - mu) * rs * g0.z + t0.z, 0.f),
                            fmaxf((v.y - mu) * rs * g0.w + t0.w, 0.f));
                v = h2f(u.z);
                u.z = pack2(fmaxf((v.x - mu) * rs * g1.x + t1.x, 0.f),
                            fmaxf((v.y - mu) * rs * g1.y + t1.y, 0.f));
                v = h2f(u.w);
                u.w = pack2(fmaxf((v.x - mu) * rs * g1.z + t1.z, 0.f),
                            fmaxf((v.y - mu) * rs * g1.w + t1.w, 0.f));
                *(uint4*)&sh[H_HE + row * 520 + cb] = u;
            }
        }
    }

    // ================= GEMM2: out = ln_relu_he @ ew2 =======================
    float c2[4][4];
    #pragma unroll
    for (int nj = 0; nj < 4; nj++)
        #pragma unroll
        for (int x = 0; x < 4; x++) c2[nj][x] = 0.f;

    for (int kc = 0; kc < 8; kc++) {
        CP_WAIT0();
        __syncthreads();
        if (kc < 7) {
            const int wb = ((kc + 1) & 1) ? H_W1 : H_W0;
            #pragma unroll
            for (int t = 0; t < 2; t++) {
                int q = t * 256 + tid;
                int n = q >> 3, k8 = (q & 7) * 8;
                cp16(sb + 2 * (wb + n * 72 + k8), g_w2h + (kc + 1) * 4096 + n * 64 + k8);
            }
            CP_COMMIT();
        }
        const int bufo = (kc & 1) ? H_W1 : H_W0;
        #pragma unroll
        for (int ks = 0; ks < 4; ks++) {
            int k0 = ks * 16;
            uint32_t a0, a1, a2, a3, p0, p1, p2, p3, q0, q1, q2, q3;
            ldm_x4(a0, a1, a2, a3,
                   sb + 2 * (H_HE + (mt + arow) * 520 + kc * 64 + k0 + ak8));
            ldm_x4(p0, p1, p2, p3, sb + 2 * (bufo + (ntw + bn) * 72 + k0 + bk8));
            ldm_x4(q0, q1, q2, q3, sb + 2 * (bufo + (ntw + 16 + bn) * 72 + k0 + bk8));
            mma_f16(c2[0], a0, a1, a2, a3, p0, p1);
            mma_f16(c2[1], a0, a1, a2, a3, p2, p3);
            mma_f16(c2[2], a0, a1, a2, a3, q0, q1);
            mma_f16(c2[3], a0, a1, a2, a3, q2, q3);
        }
    }
    __syncthreads();

    // ---- epilogue: bounce via smem (aliases E/NJ0), coalesced store ----
    #pragma unroll
    for (int nj = 0; nj < 4; nj++) {
        int cl = ntw + nj * 8 + 2 * tig;
        #pragma unroll
        for (int rr = 0; rr < 2; rr++) {
            int row = mt + g + rr * 8;
            *(float2*)&smem[F_OUT + row * 68 + cl] =
                make_float2(c2[nj][rr * 2 + 0], c2[nj][rr * 2 + 1]);
        }
    }
    __syncthreads();
    #pragma unroll
    for (int t = 0; t < 4; t++) {
        int q = t * 256 + tid;
        int r = q >> 4, c4 = (q & 15) * 4;
        float4 m = *(float4*)&smem[F_OUT + r * 68 + c4];
        size_t gbase = ((size_t)((size_t)b * NN + i) * NN + j0 + r) * EE + c4;
        float4 e4 = __ldg((const float4*)&edges[gbase]);
        float4 b4 = __ldg((const float4*)&eb2[c4]);
        float4 o = make_float4(e4.x + m.x + b4.x, e4.y + m.y + b4.y,
                               e4.z + m.z + b4.z, e4.w + m.w + b4.w);
        *(float4*)&out_edges[gbase] = o;
    }
}

// ============================================================
extern "C" void kernel_launch(void* const* d_in, const int* in_sizes, int n_in,
                              void* d_out, int out_size)
{
    const float* nodes = (const float*)d_in[0];
    const float* edges = (const float*)d_in[1];
    const float* adj   = (const float*)d_in[2];
    const float* nw1   = (const float*)d_in[3];
    const float* nb1   = (const float*)d_in[4];
    const float* ng    = (const float*)d_in[5];
    const float* nbt   = (const float*)d_in[6];
    const float* nw2   = (const float*)d_in[7];
    const float* nb2   = (const float*)d_in[8];
    const float* ew1   = (const float*)d_in[9];
    const float* eb1   = (const float*)d_in[10];
    const float* eg    = (const float*)d_in[11];
    const float* ebt   = (const float*)d_in[12];
    const float* ew2   = (const float*)d_in[13];
    const float* eb2   = (const float*)d_in[14];

    float* out_nodes = (float*)d_out;
    float* out_edges = out_nodes + (size_t)BB * NN * DD;

    cudaFuncSetAttribute(k_edge_mma, cudaFuncAttributeMaxDynamicSharedMemorySize,
                         EDGE_SMEM_BYTES);
    cudaFuncSetAttribute(k_ninj_mma, cudaFuncAttributeMaxDynamicSharedMemorySize,
                         NINJ_SMEM_BYTES);
    cudaFuncSetAttribute(k_node1, cudaFuncAttributeMaxDynamicSharedMemorySize,
                         N1_SMEM_BYTES);
    cudaFuncSetAttribute(k_node2, cudaFuncAttributeMaxDynamicSharedMemorySize,
                         N2_SMEM_BYTES);

    static cudaStream_t s2 = nullptr;
    static cudaEvent_t evFork = nullptr, evJoin = nullptr;
    if (s2 == nullptr) {
        if (cudaStreamCreateWithFlags(&s2, cudaStreamNonBlocking) != cudaSuccess)
            s2 = nullptr;
        if (s2) {
            cudaEventCreateWithFlags(&evFork, cudaEventDisableTiming);
            cudaEventCreateWithFlags(&evJoin, cudaEventDisableTiming);
        }
    }

    if (s2) {
        cudaEventRecord(evFork, 0);
        cudaStreamWaitEvent(s2, evFork, 0);
        k_node1<<<48, 256, N1_SMEM_BYTES, s2>>>(nodes, edges, adj, nw1, nb1, ng, nbt);
        k_node2<<<dim3(6, 24), 256, N2_SMEM_BYTES, s2>>>(nodes, nw2, nb2, out_nodes);
        cudaEventRecord(evJoin, s2);
        k_prep<<<296, 256>>>(ew1, ew2);
        k_ninj_mma<<<dim3(8, 24), 256, NINJ_SMEM_BYTES>>>(nodes, eb1);
        k_edge_mma<<<dim3(NN / JT, NN, BB), 256, EDGE_SMEM_BYTES>>>(edges, eg, ebt, eb2, out_edges);
        cudaStreamWaitEvent(0, evJoin, 0);
    } else {
        k_prep<<<296, 256>>>(ew1, ew2);
        k_ninj_mma<<<dim3(8, 24), 256, NINJ_SMEM_BYTES>>>(nodes, eb1);
        k_node1<<<48, 256, N1_SMEM_BYTES>>>(nodes, edges, adj, nw1, nb1, ng, nbt);
        k_node2<<<dim3(6, 24), 256, N2_SMEM_BYTES>>>(nodes, nw2, nb2, out_nodes);
        k_edge_mma<<<dim3(NN / JT, NN, BB), 256, EDGE_SMEM_BYTES>>>(edges, eg, ebt, eb2, out_edges);
    }
}

// round 16
// speedup vs baseline: 1.4364x; 1.0195x over previous
#include <cuda_runtime.h>
#include <cuda_fp16.h>
#include <cstdint>

#define BB 2
#define NN 384
#define DD 768
#define EE 64
#define HH 512
#define JT 64

// -------- scratch (no allocations allowed) --------
__device__ float  g_NI [BB * NN * HH];       // 1.5 MB
__device__ __half g_NJh[BB * NN * HH];       // 768 KB
__device__ __half g_heh[BB * NN * HH];       // 768 KB
__device__ __half g_w1h[8 * 64 * 64];        // We  chunks [ch][n][k]
__device__ __half g_w2h[8 * 64 * 64];        // ew2 chunks [kc][n][k]
__device__ __half g_wijh[2 * 512 * 768];     // Wi/Wj transposed [z][n][k]

__device__ __forceinline__ uint32_t pack2(float a, float b) {
    __half2 h = __floats2half2_rn(a, b);
    return *reinterpret_cast<uint32_t*>(&h);
}
__device__ __forceinline__ float2 h2f(uint32_t u) {
    return __half22float2(*reinterpret_cast<__half2*>(&u));
}
__device__ __forceinline__ void ldm_x4(uint32_t& r0, uint32_t& r1,
                                       uint32_t& r2, uint32_t& r3, uint32_t addr) {
    asm volatile("ldmatrix.sync.aligned.m8n8.x4.shared.b16 {%0,%1,%2,%3}, [%4];"
                 : "=r"(r0), "=r"(r1), "=r"(r2), "=r"(r3) : "r"(addr));
}
__device__ __forceinline__ void mma_f16(float c[4],
                                        uint32_t a0, uint32_t a1, uint32_t a2, uint32_t a3,
                                        uint32_t b0, uint32_t b1) {
    asm volatile("mma.sync.aligned.m16n8k16.row.col.f32.f16.f16.f32 "
        "{%0,%1,%2,%3}, {%4,%5,%6,%7}, {%8,%9}, {%0,%1,%2,%3};"
        : "+f"(c[0]), "+f"(c[1]), "+f"(c[2]), "+f"(c[3])
        : "r"(a0), "r"(a1), "r"(a2), "r"(a3), "r"(b0), "r"(b1));
}
__device__ __forceinline__ void cp16(uint32_t dst, const void* src) {
    asm volatile("cp.async.cg.shared.global [%0], [%1], 16;" :: "r"(dst), "l"(src));
}
#define CP_COMMIT() asm volatile("cp.async.commit_group;" ::: "memory")
#define CP_WAIT0()  asm volatile("cp.async.wait_group 0;" ::: "memory")

// warp-tile m16 x n32 GEMM over one k=64 chunk; B stride 72 halves
__device__ __forceinline__ void gemm_16x32(uint32_t sb, int offA, int strideA, int colA,
                                           int offB, int mt, int nt, int lane,
                                           float c[4][4]) {
    const int arow = lane & 15, ak8 = (lane >> 4) << 3;
    const int bn = (lane & 7) + ((lane >> 4) << 3);
    const int bk8 = ((lane >> 3) & 1) << 3;
    #pragma unroll
    for (int ks = 0; ks < 4; ks++) {
        int k0 = ks * 16;
        uint32_t a0, a1, a2, a3, p0, p1, p2, p3, q0, q1, q2, q3;
        ldm_x4(a0, a1, a2, a3, sb + 2 * (offA + (mt + arow) * strideA + colA + k0 + ak8));
        ldm_x4(p0, p1, p2, p3, sb + 2 * (offB + (nt + bn) * 72 + k0 + bk8));
        ldm_x4(q0, q1, q2, q3, sb + 2 * (offB + (nt + 16 + bn) * 72 + k0 + bk8));
        mma_f16(c[0], a0, a1, a2, a3, p0, p1);
        mma_f16(c[1], a0, a1, a2, a3, p2, p3);
        mma_f16(c[2], a0, a1, a2, a3, q0, q1);
        mma_f16(c[3], a0, a1, a2, a3, q2, q3);
    }
}

// ============================================================
// Kernel 0: weight pre-conversion to fp16 staging layouts
// ============================================================
__global__ __launch_bounds__(256) void k_prep(const float* __restrict__ ew1,
                                              const float* __restrict__ ew2)
{
    int idx = blockIdx.x * 256 + threadIdx.x;
    int stride = gridDim.x * 256;
    for (int i = idx; i < 8 * 64 * 64; i += stride) {
        int ch = i >> 12, r = i & 4095, n = r >> 6, k = r & 63;
        g_w1h[i] = __float2half_rn(ew1[(size_t)k * HH + ch * 64 + n]);
    }
    for (int i = idx; i < 8 * 64 * 64; i += stride) {
        int kc = i >> 12, r = i & 4095, n = r >> 6, k = r & 63;
        g_w2h[i] = __float2half_rn(ew2[(size_t)(kc * 64 + k) * EE + n]);
    }
    for (int i = idx; i < 2 * 512 * 768; i += stride) {
        int z = i / (512 * 768), r = i % (512 * 768), n = r / 768, k = r % 768;
        g_wijh[i] = __float2half_rn(ew1[(size_t)(EE + z * DD + k) * HH + n]);
    }
}

// ============================================================
// Kernel 1: NI = nodes@Wi + eb1 (fp32 out); NJ = nodes@Wj (fp16 out)
// 32-row tiles, grid (8, 24) = 192 CTAs.
// ============================================================
#define NJ_A0 0
#define NJ_A1 (32 * 72)
#define NJ_B0 (2 * 32 * 72)
#define NJ_B1 (NJ_B0 + 128 * 72)
#define NINJ_SMEM_BYTES ((NJ_B1 + 128 * 72) * 2)

__global__ __launch_bounds__(256) void k_ninj_mma(const float* __restrict__ nodes,
                                                  const float* __restrict__ eb1)
{
    extern __shared__ __half shn[];
    const uint32_t sb = (uint32_t)__cvta_generic_to_shared(shn);
    const int tid = threadIdx.x;
    const int w = tid >> 5, lane = tid & 31;
    const int g = lane >> 2, tig = lane & 3;
    const int mt = (w & 1) * 16, ntb = (w >> 1) * 32;
    const int gc = blockIdx.x * 128;
    const int r0 = blockIdx.y * 32;
    const bool is_ni = (gc < HH);
    const int z = is_ni ? 0 : 1;
    const int col0 = is_ni ? gc : (gc - HH);
    const __half* wsrc = g_wijh + (size_t)z * 512 * 768;

    float cacc[4][4];
    #pragma unroll
    for (int nj = 0; nj < 4; nj++)
        #pragma unroll
        for (int x = 0; x < 4; x++) cacc[nj][x] = 0.f;

    uint2 areg[2];
    #pragma unroll
    for (int t = 0; t < 2; t++) {
        int q = t * 256 + tid;
        int r = q >> 4, k0 = (q & 15) * 4;
        float4 v = __ldg((const float4*)&nodes[(size_t)(r0 + r) * DD + k0]);
        areg[t] = make_uint2(pack2(v.x, v.y), pack2(v.z, v.w));
    }
    #pragma unroll
    for (int t = 0; t < 4; t++) {
        int q = t * 256 + tid;
        int n = q >> 3, k8 = (q & 7) * 8;
        cp16(sb + 2 * (NJ_B0 + n * 72 + k8), wsrc + (size_t)(col0 + n) * 768 + k8);
    }
    CP_COMMIT();

    for (int kc = 0; kc < 12; kc++) {
        const int abuf = (kc & 1) ? NJ_A1 : NJ_A0;
        #pragma unroll
        for (int t = 0; t < 2; t++) {
            int q = t * 256 + tid;
            int r = q >> 4, k0 = (q & 15) * 4;
            *(uint2*)&shn[abuf + r * 72 + k0] = areg[t];
        }
        if (kc < 11) {
            #pragma unroll
            for (int t = 0; t < 2; t++) {
                int q = t * 256 + tid;
                int r = q >> 4, k0 = (q & 15) * 4;
                float4 v = __ldg((const float4*)&nodes[(size_t)(r0 + r) * DD + (kc + 1) * 64 + k0]);
                areg[t] = make_uint2(pack2(v.x, v.y), pack2(v.z, v.w));
            }
        }
        CP_WAIT0();
        __syncthreads();
        if (kc < 11) {
            const int nb = (kc & 1) ? NJ_B0 : NJ_B1;
            #pragma unroll
            for (int t = 0; t < 4; t++) {
                int q = t * 256 + tid;
                int n = q >> 3, k8 = (q & 7) * 8;
                cp16(sb + 2 * (nb + n * 72 + k8),
                     wsrc + (size_t)(col0 + n) * 768 + (kc + 1) * 64 + k8);
            }
            CP_COMMIT();
        }
        const int bbuf = (kc & 1) ? NJ_B1 : NJ_B0;
        gemm_16x32(sb, abuf, 72, 0, bbuf, mt, ntb, lane, cacc);
        __syncthreads();
    }

    #pragma unroll
    for (int nj = 0; nj < 4; nj++) {
        int coll = ntb + nj * 8 + 2 * tig;
        #pragma unroll
        for (int rr = 0; rr < 2; rr++) {
            int row = mt + g + rr * 8;
            float v0 = cacc[nj][rr * 2 + 0];
            float v1 = cacc[nj][rr * 2 + 1];
            if (is_ni) {
                float2 e = __ldg((const float2*)&eb1[gc + coll]);
                *(float2*)&g_NI[(size_t)(r0 + row) * HH + gc + coll] =
                    make_float2(v0 + e.x, v1 + e.y);
            } else {
                *(uint32_t*)&g_NJh[(size_t)(r0 + row) * HH + col0 + coll] = pack2(v0, v1);
            }
        }
    }
}

// ============================================================
// Kernel 2: node path part 1 (unchanged)
// ============================================================
#define N1_SUM 0
#define N1_SQ  16
#define N1_MU  32
#define N1_RS  48
#define N1_AGG 64
#define N1H_A  2176
#define N1H_B  (N1H_A + 16 * 72)
#define N1_SMEM_BYTES ((N1H_B + 512 * 72) * 2)

__global__ __launch_bounds__(256) void k_node1(
    const float* __restrict__ nodes, const float* __restrict__ edges,
    const float* __restrict__ adj, const float* __restrict__ nw1,
    const float* __restrict__ nb1, const float* __restrict__ ng,
    const float* __restrict__ nbt)
{
    extern __shared__ float smem[];
    __half* sh = (__half*)smem;
    const uint32_t sb = (uint32_t)__cvta_generic_to_shared(smem);
    const int tid = threadIdx.x;
    const int w = tid >> 5, lane = tid & 31;
    const int g = lane >> 2, tig = lane & 3;
    const int r0 = blockIdx.x * 16;
    const int b = r0 / NN, i0 = r0 % NN;

    if (tid < 16) { smem[N1_SUM + tid] = 0.f; smem[N1_SQ + tid] = 0.f; }

    {
        int r = tid >> 4, e4 = (tid & 15) * 4;
        const float* er = edges + (size_t)((size_t)(b * NN + i0 + r) * NN) * EE;
        const float* ar = adj + (size_t)(b * NN + i0 + r) * NN;
        float4 acc = make_float4(0.f, 0.f, 0.f, 0.f);
        for (int j = 0; j < NN; j += 4) {
            float a0 = ar[j], a1 = ar[j + 1], a2 = ar[j + 2], a3 = ar[j + 3];
            if (a0 != 0.f) { float4 v = __ldg((const float4*)&er[(size_t)j * EE + e4]);
                acc.x += v.x * a0; acc.y += v.y * a0; acc.z += v.z * a0; acc.w += v.w * a0; }
            if (a1 != 0.f) { float4 v = __ldg((const float4*)&er[(size_t)(j + 1) * EE + e4]);
                acc.x += v.x * a1; acc.y += v.y * a1; acc.z += v.z * a1; acc.w += v.w * a1; }
            if (a2 != 0.f) { float4 v = __ldg((const float4*)&er[(size_t)(j + 2) * EE + e4]);
                acc.x += v.x * a2; acc.y += v.y * a2; acc.z += v.z * a2; acc.w += v.w * a2; }
            if (a3 != 0.f) { float4 v = __ldg((const float4*)&er[(size_t)(j + 3) * EE + e4]);
                acc.x += v.x * a3; acc.y += v.y * a3; acc.z += v.z * a3; acc.w += v.w * a3; }
        }
        *(float4*)&smem[N1_AGG + r * 64 + e4] = acc;
    }
    __syncthreads();

    float cacc[2][4][4];
    #pragma unroll
    for (int s = 0; s < 2; s++)
        #pragma unroll
        for (int nj = 0; nj < 4; nj++)
            #pragma unroll
            for (int x = 0; x < 4; x++) cacc[s][nj][x] = 0.f;

    for (int kc = 0; kc < 13; kc++) {
        __syncthreads();
        {
            int r = tid >> 4, k0 = (tid & 15) * 4;
            float4 v;
            if (kc == 0) v = *(float4*)&smem[N1_AGG + r * 64 + k0];
            else {
                v = __ldg((const float4*)&nodes[(size_t)(r0 + r) * DD + (kc - 1) * 64 + k0]);
                v.x *= (float)NN; v.y *= (float)NN; v.z *= (float)NN; v.w *= (float)NN;
            }
            *(uint2*)&sh[N1H_A + r * 72 + k0] = make_uint2(pack2(v.x, v.y), pack2(v.z, v.w));
        }
        {
            int q = tid;
            for (int t = 0; t < 32; t++, q += 256) {
                int n = q & 511, k0 = (q >> 9) * 4;
                const float* p = nw1 + (size_t)(kc * 64 + k0) * HH + n;
                *(uint2*)&sh[N1H_B + n * 72 + k0] =
                    make_uint2(pack2(__ldg(p), __ldg(p + HH)),
                               pack2(__ldg(p + 2 * HH), __ldg(p + 3 * HH)));
            }
        }
        __syncthreads();
        gemm_16x32(sb, N1H_A, 72, 0, N1H_B, 0, w * 64, lane, cacc[0]);
        gemm_16x32(sb, N1H_A, 72, 0, N1H_B, 0, w * 64 + 32, lane, cacc[1]);
    }

    float rsum[2] = {0.f, 0.f}, rsq[2] = {0.f, 0.f};
    #pragma unroll
    for (int s = 0; s < 2; s++)
        #pragma unroll
        for (int nj = 0; nj < 4; nj++) {
            int coll = w * 64 + s * 32 + nj * 8 + 2 * tig;
            float2 b1 = __ldg((const float2*)&nb1[coll]);
            #pragma unroll
            for (int rr = 0; rr < 2; rr++) {
                float v0 = cacc[s][nj][rr * 2 + 0] + b1.x;
                float v1 = cacc[s][nj][rr * 2 + 1] + b1.y;
                cacc[s][nj][rr * 2 + 0] = v0;
                cacc[s][nj][rr * 2 + 1] = v1;
                rsum[rr] += v0 + v1;
                rsq[rr]  += v0 * v0 + v1 * v1;
            }
        }
    #pragma unroll
    for (int rr = 0; rr < 2; rr++) {
        float s = rsum[rr], q2 = rsq[rr];
        s  += __shfl_xor_sync(0xffffffffu, s, 1);
        s  += __shfl_xor_sync(0xffffffffu, s, 2);
        q2 += __shfl_xor_sync(0xffffffffu, q2, 1);
        q2 += __shfl_xor_sync(0xffffffffu, q2, 2);
        if (tig == 0) {
            atomicAdd(&smem[N1_SUM + g + rr * 8], s);
            atomicAdd(&smem[N1_SQ + g + rr * 8], q2);
        }
    }
    __syncthreads();
    if (tid < 16) {
        float mu = smem[N1_SUM + tid] * (1.f / HH);
        float var = smem[N1_SQ + tid] * (1.f / HH) - mu * mu;
        smem[N1_MU + tid] = mu;
        smem[N1_RS + tid] = rsqrtf(var + 1e-5f);
    }
    __syncthreads();
    const float mu0 = smem[N1_MU + g],     rs0 = smem[N1_RS + g];
    const float mu1 = smem[N1_MU + g + 8], rs1 = smem[N1_RS + g + 8];

    #pragma unroll
    for (int s = 0; s < 2; s++)
        #pragma unroll
        for (int nj = 0; nj < 4; nj++) {
            int coll = w * 64 + s * 32 + nj * 8 + 2 * tig;
            float2 gg = __ldg((const float2*)&ng[coll]);
            float2 bb = __ldg((const float2*)&nbt[coll]);
            float v0 = fmaxf((cacc[s][nj][0] - mu0) * rs0 * gg.x + bb.x, 0.f);
            float v1 = fmaxf((cacc[s][nj][1] - mu0) * rs0 * gg.y + bb.y, 0.f);
            float v2 = fmaxf((cacc[s][nj][2] - mu1) * rs1 * gg.x + bb.x, 0.f);
            float v3 = fmaxf((cacc[s][nj][3] - mu1) * rs1 * gg.y + bb.y, 0.f);
            *(uint32_t*)&sh[N1H_B + g * 520 + coll]       = pack2(v0, v1);
            *(uint32_t*)&sh[N1H_B + (g + 8) * 520 + coll] = pack2(v2, v3);
        }
    __syncthreads();
    {
        int q = tid;
        #pragma unroll
        for (int t = 0; t < 4; t++, q += 256) {
            int r = q >> 6, c0 = (q & 63) * 8;
            *(uint4*)&g_heh[(size_t)(r0 + r) * HH + c0] = *(uint4*)&sh[N1H_B + r * 520 + c0];
        }
    }
}

// ============================================================
// Kernel 3: node path part 2 (unchanged)
// ============================================================
#define N2H_HE 0
#define N2H_B  (32 * 520)
#define N2F_OUT 12928
#define N2_SMEM_BYTES ((N2F_OUT + 32 * 132) * 4)

__global__ __launch_bounds__(256) void k_node2(
    const float* __restrict__ nodes, const float* __restrict__ nw2,
    const float* __restrict__ nb2, float* __restrict__ out_nodes)
{
    extern __shared__ float smem[];
    __half* sh = (__half*)smem;
    const uint32_t sb = (uint32_t)__cvta_generic_to_shared(smem);
    const int tid = threadIdx.x;
    const int w = tid >> 5, lane = tid & 31;
    const int g = lane >> 2, tig = lane & 3;
    const int mt = (w & 1) * 16, nt = (w >> 1) * 32;
    const int nc = blockIdx.x * 128;
    const int r0 = blockIdx.y * 32;

    {
        int q = tid;
        #pragma unroll
        for (int t = 0; t < 8; t++, q += 256) {
            int r = q >> 6, c0 = (q & 63) * 8;
            *(uint4*)&sh[N2H_HE + r * 520 + c0] = *(const uint4*)&g_heh[(size_t)(r0 + r) * HH + c0];
        }
    }

    float c2[4][4];
    #pragma unroll
    for (int nj = 0; nj < 4; nj++)
        #pragma unroll
        for (int x = 0; x < 4; x++) c2[nj][x] = 0.f;

    for (int kc = 0; kc < 8; kc++) {
        __syncthreads();
        {
            int q = tid;
            #pragma unroll
            for (int t = 0; t < 8; t++, q += 256) {
                int n = q & 127, k0 = (q >> 7) * 4;
                const float* p = nw2 + (size_t)(kc * 64 + k0) * DD + nc + n;
                *(uint2*)&sh[N2H_B + n * 72 + k0] =
                    make_uint2(pack2(__ldg(p), __ldg(p + DD)),
                               pack2(__ldg(p + 2 * DD), __ldg(p + 3 * DD)));
            }
        }
        __syncthreads();
        gemm_16x32(sb, N2H_HE, 520, kc * 64, N2H_B, mt, nt, lane, c2);
    }

    __syncthreads();
    #pragma unroll
    for (int nj = 0; nj < 4; nj++) {
        int coll = nt + nj * 8 + 2 * tig;
        #pragma unroll
        for (int rr = 0; rr < 2; rr++) {
            int row = mt + g + rr * 8;
            *(float2*)&smem[N2F_OUT + row * 132 + coll] =
                make_float2(c2[nj][rr * 2 + 0], c2[nj][rr * 2 + 1]);
        }
    }
    __syncthreads();
    {
        int q = tid;
        #pragma unroll
        for (int t = 0; t < 4; t++, q += 256) {
            int r = q >> 5, c4 = (q & 31) * 4;
            float4 m = *(float4*)&smem[N2F_OUT + r * 132 + c4];
            size_t gi = (size_t)(r0 + r) * DD + nc + c4;
            float4 n4 = __ldg((const float4*)&nodes[gi]);
            float4 b4 = __ldg((const float4*)&nb2[nc + c4]);
            *(float4*)&out_nodes[gi] = make_float4(n4.x + m.x + b4.x, n4.y + m.y + b4.y,
                                                   n4.z + m.z + b4.z, n4.w + m.w + b4.w);
        }
    }
}

// ============================================================
// Kernel 4: fp16 fused edge path; raw-fragment GEMM1, warp-local
// row-coalesced NI/NJ/stats + LN passes, cp.async W staging.
// ============================================================
#define F_NI   0                     // [512] floats
#define F_OUT  768                   // [64][68] floats (aliases H_E/H_W0, dead at epilogue)
#define H_E    1536                  // half idx: [64][72]
#define H_W0   (H_E + 64 * 72)       // [64][72]
#define H_W1   (H_W0 + 64 * 72)      // [64][72]
#define H_HE   (H_W1 + 64 * 72)      // [64][520]
#define EDGE_SMEM_BYTES ((H_HE + 64 * 520) * 2)

__global__ __launch_bounds__(256, 2) void k_edge_mma(
    const float* __restrict__ edges,
    const float* __restrict__ eg,
    const float* __restrict__ ebt,
    const float* __restrict__ eb2,
    float* __restrict__ out_edges)
{
    extern __shared__ float smem[];
    __half* sh = (__half*)smem;
    const uint32_t sb = (uint32_t)__cvta_generic_to_shared(smem);
    const int tid = threadIdx.x;
    const int w = tid >> 5, lane = tid & 31;
    const int g = lane >> 2, tig = lane & 3;
    const int mt = (w & 3) * 16, ntw = (w >> 2) * 32;
    const int b = blockIdx.z, i = blockIdx.y;
    const int j0 = blockIdx.x * JT;

    const int arow = lane & 15, ak8 = (lane >> 4) << 3;
    const int bn = (lane & 7) + ((lane >> 4) << 3);
    const int bk8 = ((lane >> 3) & 1) << 3;

    const __half* njb = g_NJh + (size_t)((size_t)b * NN + j0) * HH;

    // ---- stage E [64][72] fp16 ----
    const float* etile = edges + ((size_t)((size_t)b * NN + i) * NN + j0) * EE;
    #pragma unroll
    for (int t = 0; t < 4; t++) {
        int q = t * 256 + tid;
        int j = q >> 4, k0 = (q & 15) * 4;
        float4 v = __ldg((const float4*)&etile[j * EE + k0]);
        *(uint2*)&sh[H_E + j * 72 + k0] = make_uint2(pack2(v.x, v.y), pack2(v.z, v.w));
    }
    // ---- NI cache ----
    const float* nip = g_NI + (size_t)((size_t)b * NN + i) * HH;
    smem[F_NI + tid] = __ldg(&nip[tid]);
    smem[F_NI + 256 + tid] = __ldg(&nip[256 + tid]);

    // issue W1 ch0 -> H_W0
    #pragma unroll
    for (int t = 0; t < 2; t++) {
        int q = t * 256 + tid;
        int n = q >> 3, k8 = (q & 7) * 8;
        cp16(sb + 2 * (H_W0 + n * 72 + k8), g_w1h + n * 64 + k8);
    }
    CP_COMMIT();
    __syncthreads();                           // E + NI visible

    // ---- hoist E fragments ----
    uint32_t ef[4][4];
    #pragma unroll
    for (int ks = 0; ks < 4; ks++)
        ldm_x4(ef[ks][0], ef[ks][1], ef[ks][2], ef[ks][3],
               sb + 2 * (H_E + (mt + arow) * 72 + ks * 16 + ak8));

    // ================= GEMM1: raw he = E@We -> sHe =========================
    for (int ch = 0; ch < 8; ch++) {
        CP_WAIT0();
        __syncthreads();                       // W_ch visible; prev consume done
        if (ch < 7) {
            const int wb = ((ch + 1) & 1) ? H_W1 : H_W0;
            #pragma unroll
            for (int t = 0; t < 2; t++) {
                int q = t * 256 + tid;
                int n = q >> 3, k8 = (q & 7) * 8;
                cp16(sb + 2 * (wb + n * 72 + k8), g_w1h + (ch + 1) * 4096 + n * 64 + k8);
            }
            CP_COMMIT();
        }
        const int bufo = (ch & 1) ? H_W1 : H_W0;
        float c[4][4];
        #pragma unroll
        for (int nj = 0; nj < 4; nj++)
            #pragma unroll
            for (int x = 0; x < 4; x++) c[nj][x] = 0.f;
        #pragma unroll
        for (int ks = 0; ks < 4; ks++) {
            int k0 = ks * 16;
            uint32_t p0, p1, p2, p3, q0, q1, q2, q3;
            ldm_x4(p0, p1, p2, p3, sb + 2 * (bufo + (ntw + bn) * 72 + k0 + bk8));
            ldm_x4(q0, q1, q2, q3, sb + 2 * (bufo + (ntw + 16 + bn) * 72 + k0 + bk8));
            mma_f16(c[0], ef[ks][0], ef[ks][1], ef[ks][2], ef[ks][3], p0, p1);
            mma_f16(c[1], ef[ks][0], ef[ks][1], ef[ks][2], ef[ks][3], p2, p3);
            mma_f16(c[2], ef[ks][0], ef[ks][1], ef[ks][2], ef[ks][3], q0, q1);
            mma_f16(c[3], ef[ks][0], ef[ks][1], ef[ks][2], ef[ks][3], q2, q3);
        }
        // raw fragment store only
        #pragma unroll
        for (int nj = 0; nj < 4; nj++) {
            int cl = ntw + nj * 8 + 2 * tig;
            #pragma unroll
            for (int rr = 0; rr < 2; rr++) {
                int row = mt + g + rr * 8;
                *(uint32_t*)&sh[H_HE + row * 520 + ch * 64 + cl] =
                    pack2(c[nj][rr * 2 + 0], c[nj][rr * 2 + 1]);
            }
        }
    }
    __syncthreads();                           // all raw he visible

    // issue W2 chunk0 early (overlaps the two row passes)
    #pragma unroll
    for (int t = 0; t < 2; t++) {
        int q = t * 256 + tid;
        int n = q >> 3, k8 = (q & 7) * 8;
        cp16(sb + 2 * (H_W0 + n * 72 + k8), g_w2h + n * 64 + k8);
    }
    CP_COMMIT();

    // ---- warp-local pass A: he += NI + NJ (row-coalesced), stats ----
    {
        const int wr = w * 8;                  // this warp's 8 rows
        float s8[8], q8[8];
        #pragma unroll
        for (int r = 0; r < 8; r++) { s8[r] = 0.f; q8[r] = 0.f; }
        #pragma unroll
        for (int pass = 0; pass < 2; pass++) {
            int cb = pass * 256 + lane * 8;
            float4 ni0 = *(float4*)&smem[F_NI + cb];
            float4 ni1 = *(float4*)&smem[F_NI + cb + 4];
            #pragma unroll
            for (int r = 0; r < 8; r++) {
                int row = wr + r;
                uint4 m4 = *(uint4*)&sh[H_HE + row * 520 + cb];
                uint4 n4 = __ldg((const uint4*)&njb[(size_t)row * HH + cb]);
                float2 a, nv;
                a = h2f(m4.x); nv = h2f(n4.x);
                float v0 = a.x + ni0.x + nv.x, v1 = a.y + ni0.y + nv.y;
                a = h2f(m4.y); nv = h2f(n4.y);
                float v2 = a.x + ni0.z + nv.x, v3 = a.y + ni0.w + nv.y;
                a = h2f(m4.z); nv = h2f(n4.z);
                float v4 = a.x + ni1.x + nv.x, v5 = a.y + ni1.y + nv.y;
                a = h2f(m4.w); nv = h2f(n4.w);
                float v6 = a.x + ni1.z + nv.x, v7 = a.y + ni1.w + nv.y;
                s8[r] += v0 + v1 + v2 + v3 + v4 + v5 + v6 + v7;
                q8[r] += v0*v0 + v1*v1 + v2*v2 + v3*v3 + v4*v4 + v5*v5 + v6*v6 + v7*v7;
                m4.x = pack2(v0, v1); m4.y = pack2(v2, v3);
                m4.z = pack2(v4, v5); m4.w = pack2(v6, v7);
                *(uint4*)&sh[H_HE + row * 520 + cb] = m4;
            }
        }
        float mus[8], rss[8];
        #pragma unroll
        for (int r = 0; r < 8; r++) {
            float s = s8[r], q2 = q8[r];
            #pragma unroll
            for (int m = 16; m >= 1; m >>= 1) {
                s  += __shfl_xor_sync(0xffffffffu, s, m);
                q2 += __shfl_xor_sync(0xffffffffu, q2, m);
            }
            float mu = s * (1.f / HH);
            mus[r] = mu;
            rss[r] = rsqrtf(q2 * (1.f / HH) - mu * mu + 1e-5f);
        }

        // ---- warp-local LN + relu sweep (no cross-warp sync needed) ----
        #pragma unroll
        for (int pass = 0; pass < 2; pass++) {
            int cb = pass * 256 + lane * 8;
            float4 g0 = __ldg((const float4*)&eg[cb]);
            float4 g1 = __ldg((const float4*)&eg[cb + 4]);
            float4 t0 = __ldg((const float4*)&ebt[cb]);
            float4 t1 = __ldg((const float4*)&ebt[cb + 4]);
            #pragma unroll
            for (int r = 0; r < 8; r++) {
                int row = wr + r;
                float mu = mus[r], rs = rss[r];
                uint4 u = *(uint4*)&sh[H_HE + row * 520 + cb];
                float2 v;
                v = h2f(u.x);
                u.x = pack2(fmaxf((v.x - mu) * rs * g0.x + t0.x, 0.f),
                            fmaxf((v.y - mu) * rs * g0.y + t0.y, 0.f));
                v = h2f(u.y);
                u.y = pack2(fmaxf((v.x - mu) * rs * g0.z + t0.z, 0.f),
                            fmaxf((v.y - mu) * rs * g0.w + t0.w, 0.f));
                v = h2f(u.z);
                u.z = pack2(fmaxf((v.x - mu) * rs * g1.x + t1.x, 0.f),
                            fmaxf((v.y - mu) * rs * g1.y + t1.y, 0.f));
                v = h2f(u.w);
                u.w = pack2(fmaxf((v.x - mu) * rs * g1.z + t1.z, 0.f),
                            fmaxf((v.y - mu) * rs * g1.w + t1.w, 0.f));
                *(uint4*)&sh[H_HE + row * 520 + cb] = u;
            }
        }
    }
    __syncthreads();                           // he' visible to all warps

    // ================= GEMM2: out = ln_relu_he @ ew2 =======================
    float c2[4][4];
    #pragma unroll
    for (int nj = 0; nj < 4; nj++)
        #pragma unroll
        for (int x = 0; x < 4; x++) c2[nj][x] = 0.f;

    for (int kc = 0; kc < 8; kc++) {
        CP_WAIT0();
        __syncthreads();
        if (kc < 7) {
            const int wb = ((kc + 1) & 1) ? H_W1 : H_W0;
            #pragma unroll
            for (int t = 0; t < 2; t++) {
                int q = t * 256 + tid;
                int n = q >> 3, k8 = (q & 7) * 8;
                cp16(sb + 2 * (wb + n * 72 + k8), g_w2h + (kc + 1) * 4096 + n * 64 + k8);
            }
            CP_COMMIT();
        }
        const int bufo = (kc & 1) ? H_W1 : H_W0;
        #pragma unroll
        for (int ks = 0; ks < 4; ks++) {
            int k0 = ks * 16;
            uint32_t a0, a1, a2, a3, p0, p1, p2, p3, q0, q1, q2, q3;
            ldm_x4(a0, a1, a2, a3,
                   sb + 2 * (H_HE + (mt + arow) * 520 + kc * 64 + k0 + ak8));
            ldm_x4(p0, p1, p2, p3, sb + 2 * (bufo + (ntw + bn) * 72 + k0 + bk8));
            ldm_x4(q0, q1, q2, q3, sb + 2 * (bufo + (ntw + 16 + bn) * 72 + k0 + bk8));
            mma_f16(c2[0], a0, a1, a2, a3, p0, p1);
            mma_f16(c2[1], a0, a1, a2, a3, p2, p3);
            mma_f16(c2[2], a0, a1, a2, a3, q0, q1);
            mma_f16(c2[3], a0, a1, a2, a3, q2, q3);
        }
    }
    __syncthreads();

    // ---- epilogue: bounce via smem, coalesced residual + store ----
    #pragma unroll
    for (int nj = 0; nj < 4; nj++) {
        int cl = ntw + nj * 8 + 2 * tig;
        #pragma unroll
        for (int rr = 0; rr < 2; rr++) {
            int row = mt + g + rr * 8;
            *(float2*)&smem[F_OUT + row * 68 + cl] =
                make_float2(c2[nj][rr * 2 + 0], c2[nj][rr * 2 + 1]);
        }
    }
    __syncthreads();
    #pragma unroll
    for (int t = 0; t < 4; t++) {
        int q = t * 256 + tid;
        int r = q >> 4, c4 = (q & 15) * 4;
        float4 m = *(float4*)&smem[F_OUT + r * 68 + c4];
        size_t gbase = ((size_t)((size_t)b * NN + i) * NN + j0 + r) * EE + c4;
        float4 e4 = __ldg((const float4*)&edges[gbase]);
        float4 b4 = __ldg((const float4*)&eb2[c4]);
        float4 o = make_float4(e4.x + m.x + b4.x, e4.y + m.y + b4.y,
                               e4.z + m.z + b4.z, e4.w + m.w + b4.w);
        *(float4*)&out_edges[gbase] = o;
    }
}

// ============================================================
extern "C" void kernel_launch(void* const* d_in, const int* in_sizes, int n_in,
                              void* d_out, int out_size)
{
    const float* nodes = (const float*)d_in[0];
    const float* edges = (const float*)d_in[1];
    const float* adj   = (const float*)d_in[2];
    const float* nw1   = (const float*)d_in[3];
    const float* nb1   = (const float*)d_in[4];
    const float* ng    = (const float*)d_in[5];
    const float* nbt   = (const float*)d_in[6];
    const float* nw2   = (const float*)d_in[7];
    const float* nb2   = (const float*)d_in[8];
    const float* ew1   = (const float*)d_in[9];
    const float* eb1   = (const float*)d_in[10];
    const float* eg    = (const float*)d_in[11];
    const float* ebt   = (const float*)d_in[12];
    const float* ew2   = (const float*)d_in[13];
    const float* eb2   = (const float*)d_in[14];

    float* out_nodes = (float*)d_out;
    float* out_edges = out_nodes + (size_t)BB * NN * DD;

    cudaFuncSetAttribute(k_edge_mma, cudaFuncAttributeMaxDynamicSharedMemorySize,
                         EDGE_SMEM_BYTES);
    cudaFuncSetAttribute(k_ninj_mma, cudaFuncAttributeMaxDynamicSharedMemorySize,
                         NINJ_SMEM_BYTES);
    cudaFuncSetAttribute(k_node1, cudaFuncAttributeMaxDynamicSharedMemorySize,
                         N1_SMEM_BYTES);
    cudaFuncSetAttribute(k_node2, cudaFuncAttributeMaxDynamicSharedMemorySize,
                         N2_SMEM_BYTES);

    static cudaStream_t s2 = nullptr;
    static cudaEvent_t evFork = nullptr, evJoin = nullptr;
    if (s2 == nullptr) {
        if (cudaStreamCreateWithFlags(&s2, cudaStreamNonBlocking) != cudaSuccess)
            s2 = nullptr;
        if (s2) {
            cudaEventCreateWithFlags(&evFork, cudaEventDisableTiming);
            cudaEventCreateWithFlags(&evJoin, cudaEventDisableTiming);
        }
    }

    if (s2) {
        cudaEventRecord(evFork, 0);
        cudaStreamWaitEvent(s2, evFork, 0);
        k_node1<<<48, 256, N1_SMEM_BYTES, s2>>>(nodes, edges, adj, nw1, nb1, ng, nbt);
        k_node2<<<dim3(6, 24), 256, N2_SMEM_BYTES, s2>>>(nodes, nw2, nb2, out_nodes);
        cudaEventRecord(evJoin, s2);
        k_prep<<<296, 256>>>(ew1, ew2);
        k_ninj_mma<<<dim3(8, 24), 256, NINJ_SMEM_BYTES>>>(nodes, eb1);
        k_edge_mma<<<dim3(NN / JT, NN, BB), 256, EDGE_SMEM_BYTES>>>(edges, eg, ebt, eb2, out_edges);
        cudaStreamWaitEvent(0, evJoin, 0);
    } else {
        k_prep<<<296, 256>>>(ew1, ew2);
        k_ninj_mma<<<dim3(8, 24), 256, NINJ_SMEM_BYTES>>>(nodes, eb1);
        k_node1<<<48, 256, N1_SMEM_BYTES>>>(nodes, edges, adj, nw1, nb1, ng, nbt);
        k_node2<<<dim3(6, 24), 256, N2_SMEM_BYTES>>>(nodes, nw2, nb2, out_nodes);
        k_edge_mma<<<dim3(NN / JT, NN, BB), 256, EDGE_SMEM_BYTES>>>(edges, eg, ebt, eb2, out_edges);
    }
}

// round 17
// speedup vs baseline: 1.4641x; 1.0193x over previous
#include <cuda_runtime.h>
#include <cuda_fp16.h>
#include <cstdint>

#define BB 2
#define NN 384
#define DD 768
#define EE 64
#define HH 512
#define JT 64

// -------- scratch (no allocations allowed) --------
__device__ float  g_NI [BB * NN * HH];       // 1.5 MB
__device__ __half g_NJh[BB * NN * HH];       // 768 KB
__device__ __half g_heh[BB * NN * HH];       // 768 KB
__device__ __half g_w1h[8 * 64 * 64];        // We  chunks [ch][n][k]
__device__ __half g_w2h[8 * 64 * 64];        // ew2 chunks [kc][n][k]
__device__ __half g_wijh[2 * 512 * 768];     // Wi/Wj transposed [z][n][k]
__device__ __half g_ndh[BB * NN * DD];       // nodes fp16

__device__ __forceinline__ uint32_t pack2(float a, float b) {
    __half2 h = __floats2half2_rn(a, b);
    return *reinterpret_cast<uint32_t*>(&h);
}
__device__ __forceinline__ float2 h2f(uint32_t u) {
    return __half22float2(*reinterpret_cast<__half2*>(&u));
}
__device__ __forceinline__ void ldm_x4(uint32_t& r0, uint32_t& r1,
                                       uint32_t& r2, uint32_t& r3, uint32_t addr) {
    asm volatile("ldmatrix.sync.aligned.m8n8.x4.shared.b16 {%0,%1,%2,%3}, [%4];"
                 : "=r"(r0), "=r"(r1), "=r"(r2), "=r"(r3) : "r"(addr));
}
__device__ __forceinline__ void mma_f16(float c[4],
                                        uint32_t a0, uint32_t a1, uint32_t a2, uint32_t a3,
                                        uint32_t b0, uint32_t b1) {
    asm volatile("mma.sync.aligned.m16n8k16.row.col.f32.f16.f16.f32 "
        "{%0,%1,%2,%3}, {%4,%5,%6,%7}, {%8,%9}, {%0,%1,%2,%3};"
        : "+f"(c[0]), "+f"(c[1]), "+f"(c[2]), "+f"(c[3])
        : "r"(a0), "r"(a1), "r"(a2), "r"(a3), "r"(b0), "r"(b1));
}
__device__ __forceinline__ void cp16(uint32_t dst, const void* src) {
    asm volatile("cp.async.cg.shared.global [%0], [%1], 16;" :: "r"(dst), "l"(src));
}
#define CP_COMMIT() asm volatile("cp.async.commit_group;" ::: "memory")
#define CP_WAIT0()  asm volatile("cp.async.wait_group 0;" ::: "memory")
#define CP_WAIT1()  asm volatile("cp.async.wait_group 1;" ::: "memory")

// warp-tile m16 x n32 GEMM over one k=64 chunk; B stride 72 halves
__device__ __forceinline__ void gemm_16x32(uint32_t sb, int offA, int strideA, int colA,
                                           int offB, int mt, int nt, int lane,
                                           float c[4][4]) {
    const int arow = lane & 15, ak8 = (lane >> 4) << 3;
    const int bn = (lane & 7) + ((lane >> 4) << 3);
    const int bk8 = ((lane >> 3) & 1) << 3;
    #pragma unroll
    for (int ks = 0; ks < 4; ks++) {
        int k0 = ks * 16;
        uint32_t a0, a1, a2, a3, p0, p1, p2, p3, q0, q1, q2, q3;
        ldm_x4(a0, a1, a2, a3, sb + 2 * (offA + (mt + arow) * strideA + colA + k0 + ak8));
        ldm_x4(p0, p1, p2, p3, sb + 2 * (offB + (nt + bn) * 72 + k0 + bk8));
        ldm_x4(q0, q1, q2, q3, sb + 2 * (offB + (nt + 16 + bn) * 72 + k0 + bk8));
        mma_f16(c[0], a0, a1, a2, a3, p0, p1);
        mma_f16(c[1], a0, a1, a2, a3, p2, p3);
        mma_f16(c[2], a0, a1, a2, a3, q0, q1);
        mma_f16(c[3], a0, a1, a2, a3, q2, q3);
    }
}

// ============================================================
// Kernel 0: weight + nodes pre-conversion to fp16 staging layouts
// ============================================================
__global__ __launch_bounds__(256) void k_prep(const float* __restrict__ nodes,
                                              const float* __restrict__ ew1,
                                              const float* __restrict__ ew2)
{
    int idx = blockIdx.x * 256 + threadIdx.x;
    int stride = gridDim.x * 256;
    for (int i = idx; i < 8 * 64 * 64; i += stride) {
        int ch = i >> 12, r = i & 4095, n = r >> 6, k = r & 63;
        g_w1h[i] = __float2half_rn(ew1[(size_t)k * HH + ch * 64 + n]);
    }
    for (int i = idx; i < 8 * 64 * 64; i += stride) {
        int kc = i >> 12, r = i & 4095, n = r >> 6, k = r & 63;
        g_w2h[i] = __float2half_rn(ew2[(size_t)(kc * 64 + k) * EE + n]);
    }
    for (int i = idx; i < 2 * 512 * 768; i += stride) {
        int z = i / (512 * 768), r = i % (512 * 768), n = r / 768, k = r % 768;
        g_wijh[i] = __float2half_rn(ew1[(size_t)(EE + z * DD + k) * HH + n]);
    }
    for (int i = idx; i < BB * NN * DD; i += stride)
        g_ndh[i] = __float2half_rn(nodes[i]);
}

// ============================================================
// Kernel 1: NI = nodes@Wi + eb1 (fp32 out); NJ = nodes@Wj (fp16 out)
// 16-row tiles, grid (8, 48) = 384 CTAs, 3-stage cp.async.
// ============================================================
#define NJ_A(s) ((s) * (16 * 72))
#define NJ_B(s) (3 * 16 * 72 + (s) * (128 * 72))
#define NINJ_SMEM_BYTES ((3 * 16 * 72 + 3 * 128 * 72) * 2)

__global__ __launch_bounds__(256) void k_ninj_mma(const float* __restrict__ eb1)
{
    extern __shared__ __half shn[];
    const uint32_t sb = (uint32_t)__cvta_generic_to_shared(shn);
    const int tid = threadIdx.x;
    const int w = tid >> 5, lane = tid & 31;
    const int g = lane >> 2, tig = lane & 3;
    const int ntb = w * 16;
    const int gc = blockIdx.x * 128;
    const int r0 = blockIdx.y * 16;
    const bool is_ni = (gc < HH);
    const int z = is_ni ? 0 : 1;
    const int col0 = is_ni ? gc : (gc - HH);
    const __half* wsrc = g_wijh + (size_t)z * 512 * 768;
    const __half* asrc = g_ndh + (size_t)r0 * DD;

    const int arow = lane & 15, ak8 = (lane >> 4) << 3;
    const int bn = (lane & 7) + ((lane >> 4) << 3);
    const int bk8 = ((lane >> 3) & 1) << 3;

    float cacc[2][4];
    #pragma unroll
    for (int nj = 0; nj < 2; nj++)
        #pragma unroll
        for (int x = 0; x < 4; x++) cacc[nj][x] = 0.f;

    // issue chunk kc into stage s
    #define NINJ_ISSUE(kc, s) do { \
        if (tid < 128) { \
            int n_ = tid >> 3, k8_ = (tid & 7) * 8; \
            cp16(sb + 2 * (NJ_A(s) + n_ * 72 + k8_), asrc + (size_t)n_ * DD + (kc) * 64 + k8_); \
        } \
        _Pragma("unroll") \
        for (int t_ = 0; t_ < 4; t_++) { \
            int q_ = t_ * 256 + tid; \
            int n_ = q_ >> 3, k8_ = (q_ & 7) * 8; \
            cp16(sb + 2 * (NJ_B(s) + n_ * 72 + k8_), \
                 wsrc + (size_t)(col0 + n_) * 768 + (kc) * 64 + k8_); \
        } \
        CP_COMMIT(); \
    } while (0)

    NINJ_ISSUE(0, 0);
    NINJ_ISSUE(1, 1);

    for (int kc = 0; kc < 12; kc++) {
        if (kc < 11) CP_WAIT1(); else CP_WAIT0();
        __syncthreads();
        if (kc + 2 < 12) NINJ_ISSUE(kc + 2, (kc + 2) % 3);
        const int s = kc % 3;
        #pragma unroll
        for (int ks = 0; ks < 4; ks++) {
            int k0 = ks * 16;
            uint32_t a0, a1, a2, a3, p0, p1, p2, p3;
            ldm_x4(a0, a1, a2, a3, sb + 2 * (NJ_A(s) + arow * 72 + k0 + ak8));
            ldm_x4(p0, p1, p2, p3, sb + 2 * (NJ_B(s) + (ntb + bn) * 72 + k0 + bk8));
            mma_f16(cacc[0], a0, a1, a2, a3, p0, p1);
            mma_f16(cacc[1], a0, a1, a2, a3, p2, p3);
        }
    }

    #pragma unroll
    for (int nj = 0; nj < 2; nj++) {
        int coll = ntb + nj * 8 + 2 * tig;
        #pragma unroll
        for (int rr = 0; rr < 2; rr++) {
            int row = g + rr * 8;
            float v0 = cacc[nj][rr * 2 + 0];
            float v1 = cacc[nj][rr * 2 + 1];
            if (is_ni) {
                float2 e = __ldg((const float2*)&eb1[gc + coll]);
                *(float2*)&g_NI[(size_t)(r0 + row) * HH + gc + coll] =
                    make_float2(v0 + e.x, v1 + e.y);
            } else {
                *(uint32_t*)&g_NJh[(size_t)(r0 + row) * HH + col0 + coll] = pack2(v0, v1);
            }
        }
    }
}

// ============================================================
// Kernel 2: node path part 1 (unchanged)
// ============================================================
#define N1_SUM 0
#define N1_SQ  16
#define N1_MU  32
#define N1_RS  48
#define N1_AGG 64
#define N1H_A  2176
#define N1H_B  (N1H_A + 16 * 72)
#define N1_SMEM_BYTES ((N1H_B + 512 * 72) * 2)

__global__ __launch_bounds__(256) void k_node1(
    const float* __restrict__ nodes, const float* __restrict__ edges,
    const float* __restrict__ adj, const float* __restrict__ nw1,
    const float* __restrict__ nb1, const float* __restrict__ ng,
    const float* __restrict__ nbt)
{
    extern __shared__ float smem[];
    __half* sh = (__half*)smem;
    const uint32_t sb = (uint32_t)__cvta_generic_to_shared(smem);
    const int tid = threadIdx.x;
    const int w = tid >> 5, lane = tid & 31;
    const int g = lane >> 2, tig = lane & 3;
    const int r0 = blockIdx.x * 16;
    const int b = r0 / NN, i0 = r0 % NN;

    if (tid < 16) { smem[N1_SUM + tid] = 0.f; smem[N1_SQ + tid] = 0.f; }

    {
        int r = tid >> 4, e4 = (tid & 15) * 4;
        const float* er = edges + (size_t)((size_t)(b * NN + i0 + r) * NN) * EE;
        const float* ar = adj + (size_t)(b * NN + i0 + r) * NN;
        float4 acc = make_float4(0.f, 0.f, 0.f, 0.f);
        for (int j = 0; j < NN; j += 4) {
            float a0 = ar[j], a1 = ar[j + 1], a2 = ar[j + 2], a3 = ar[j + 3];
            if (a0 != 0.f) { float4 v = __ldg((const float4*)&er[(size_t)j * EE + e4]);
                acc.x += v.x * a0; acc.y += v.y * a0; acc.z += v.z * a0; acc.w += v.w * a0; }
            if (a1 != 0.f) { float4 v = __ldg((const float4*)&er[(size_t)(j + 1) * EE + e4]);
                acc.x += v.x * a1; acc.y += v.y * a1; acc.z += v.z * a1; acc.w += v.w * a1; }
            if (a2 != 0.f) { float4 v = __ldg((const float4*)&er[(size_t)(j + 2) * EE + e4]);
                acc.x += v.x * a2; acc.y += v.y * a2; acc.z += v.z * a2; acc.w += v.w * a2; }
            if (a3 != 0.f) { float4 v = __ldg((const float4*)&er[(size_t)(j + 3) * EE + e4]);
                acc.x += v.x * a3; acc.y += v.y * a3; acc.z += v.z * a3; acc.w += v.w * a3; }
        }
        *(float4*)&smem[N1_AGG + r * 64 + e4] = acc;
    }
    __syncthreads();

    float cacc[2][4][4];
    #pragma unroll
    for (int s = 0; s < 2; s++)
        #pragma unroll
        for (int nj = 0; nj < 4; nj++)
            #pragma unroll
            for (int x = 0; x < 4; x++) cacc[s][nj][x] = 0.f;

    for (int kc = 0; kc < 13; kc++) {
        __syncthreads();
        {
            int r = tid >> 4, k0 = (tid & 15) * 4;
            float4 v;
            if (kc == 0) v = *(float4*)&smem[N1_AGG + r * 64 + k0];
            else {
                v = __ldg((const float4*)&nodes[(size_t)(r0 + r) * DD + (kc - 1) * 64 + k0]);
                v.x *= (float)NN; v.y *= (float)NN; v.z *= (float)NN; v.w *= (float)NN;
            }
            *(uint2*)&sh[N1H_A + r * 72 + k0] = make_uint2(pack2(v.x, v.y), pack2(v.z, v.w));
        }
        {
            int q = tid;
            for (int t = 0; t < 32; t++, q += 256) {
                int n = q & 511, k0 = (q >> 9) * 4;
                const float* p = nw1 + (size_t)(kc * 64 + k0) * HH + n;
                *(uint2*)&sh[N1H_B + n * 72 + k0] =
                    make_uint2(pack2(__ldg(p), __ldg(p + HH)),
                               pack2(__ldg(p + 2 * HH), __ldg(p + 3 * HH)));
            }
        }
        __syncthreads();
        gemm_16x32(sb, N1H_A, 72, 0, N1H_B, 0, w * 64, lane, cacc[0]);
        gemm_16x32(sb, N1H_A, 72, 0, N1H_B, 0, w * 64 + 32, lane, cacc[1]);
    }

    float rsum[2] = {0.f, 0.f}, rsq[2] = {0.f, 0.f};
    #pragma unroll
    for (int s = 0; s < 2; s++)
        #pragma unroll
        for (int nj = 0; nj < 4; nj++) {
            int coll = w * 64 + s * 32 + nj * 8 + 2 * tig;
            float2 b1 = __ldg((const float2*)&nb1[coll]);
            #pragma unroll
            for (int rr = 0; rr < 2; rr++) {
                float v0 = cacc[s][nj][rr * 2 + 0] + b1.x;
                float v1 = cacc[s][nj][rr * 2 + 1] + b1.y;
                cacc[s][nj][rr * 2 + 0] = v0;
                cacc[s][nj][rr * 2 + 1] = v1;
                rsum[rr] += v0 + v1;
                rsq[rr]  += v0 * v0 + v1 * v1;
            }
        }
    #pragma unroll
    for (int rr = 0; rr < 2; rr++) {
        float s = rsum[rr], q2 = rsq[rr];
        s  += __shfl_xor_sync(0xffffffffu, s, 1);
        s  += __shfl_xor_sync(0xffffffffu, s, 2);
        q2 += __shfl_xor_sync(0xffffffffu, q2, 1);
        q2 += __shfl_xor_sync(0xffffffffu, q2, 2);
        if (tig == 0) {
            atomicAdd(&smem[N1_SUM + g + rr * 8], s);
            atomicAdd(&smem[N1_SQ + g + rr * 8], q2);
        }
    }
    __syncthreads();
    if (tid < 16) {
        float mu = smem[N1_SUM + tid] * (1.f / HH);
        float var = smem[N1_SQ + tid] * (1.f / HH) - mu * mu;
        smem[N1_MU + tid] = mu;
        smem[N1_RS + tid] = rsqrtf(var + 1e-5f);
    }
    __syncthreads();
    const float mu0 = smem[N1_MU + g],     rs0 = smem[N1_RS + g];
    const float mu1 = smem[N1_MU + g + 8], rs1 = smem[N1_RS + g + 8];

    #pragma unroll
    for (int s = 0; s < 2; s++)
        #pragma unroll
        for (int nj = 0; nj < 4; nj++) {
            int coll = w * 64 + s * 32 + nj * 8 + 2 * tig;
            float2 gg = __ldg((const float2*)&ng[coll]);
            float2 bb = __ldg((const float2*)&nbt[coll]);
            float v0 = fmaxf((cacc[s][nj][0] - mu0) * rs0 * gg.x + bb.x, 0.f);
            float v1 = fmaxf((cacc[s][nj][1] - mu0) * rs0 * gg.y + bb.y, 0.f);
            float v2 = fmaxf((cacc[s][nj][2] - mu1) * rs1 * gg.x + bb.x, 0.f);
            float v3 = fmaxf((cacc[s][nj][3] - mu1) * rs1 * gg.y + bb.y, 0.f);
            *(uint32_t*)&sh[N1H_B + g * 520 + coll]       = pack2(v0, v1);
            *(uint32_t*)&sh[N1H_B + (g + 8) * 520 + coll] = pack2(v2, v3);
        }
    __syncthreads();
    {
        int q = tid;
        #pragma unroll
        for (int t = 0; t < 4; t++, q += 256) {
            int r = q >> 6, c0 = (q & 63) * 8;
            *(uint4*)&g_heh[(size_t)(r0 + r) * HH + c0] = *(uint4*)&sh[N1H_B + r * 520 + c0];
        }
    }
}

// ============================================================
// Kernel 3: node path part 2 (unchanged)
// ============================================================
#define N2H_HE 0
#define N2H_B  (32 * 520)
#define N2F_OUT 12928
#define N2_SMEM_BYTES ((N2F_OUT + 32 * 132) * 4)

__global__ __launch_bounds__(256) void k_node2(
    const float* __restrict__ nodes, const float* __restrict__ nw2,
    const float* __restrict__ nb2, float* __restrict__ out_nodes)
{
    extern __shared__ float smem[];
    __half* sh = (__half*)smem;
    const uint32_t sb = (uint32_t)__cvta_generic_to_shared(smem);
    const int tid = threadIdx.x;
    const int w = tid >> 5, lane = tid & 31;
    const int g = lane >> 2, tig = lane & 3;
    const int mt = (w & 1) * 16, nt = (w >> 1) * 32;
    const int nc = blockIdx.x * 128;
    const int r0 = blockIdx.y * 32;

    {
        int q = tid;
        #pragma unroll
        for (int t = 0; t < 8; t++, q += 256) {
            int r = q >> 6, c0 = (q & 63) * 8;
            *(uint4*)&sh[N2H_HE + r * 520 + c0] = *(const uint4*)&g_heh[(size_t)(r0 + r) * HH + c0];
        }
    }

    float c2[4][4];
    #pragma unroll
    for (int nj = 0; nj < 4; nj++)
        #pragma unroll
        for (int x = 0; x < 4; x++) c2[nj][x] = 0.f;

    for (int kc = 0; kc < 8; kc++) {
        __syncthreads();
        {
            int q = tid;
            #pragma unroll
            for (int t = 0; t < 8; t++, q += 256) {
                int n = q & 127, k0 = (q >> 7) * 4;
                const float* p = nw2 + (size_t)(kc * 64 + k0) * DD + nc + n;
                *(uint2*)&sh[N2H_B + n * 72 + k0] =
                    make_uint2(pack2(__ldg(p), __ldg(p + DD)),
                               pack2(__ldg(p + 2 * DD), __ldg(p + 3 * DD)));
            }
        }
        __syncthreads();
        gemm_16x32(sb, N2H_HE, 520, kc * 64, N2H_B, mt, nt, lane, c2);
    }

    __syncthreads();
    #pragma unroll
    for (int nj = 0; nj < 4; nj++) {
        int coll = nt + nj * 8 + 2 * tig;
        #pragma unroll
        for (int rr = 0; rr < 2; rr++) {
            int row = mt + g + rr * 8;
            *(float2*)&smem[N2F_OUT + row * 132 + coll] =
                make_float2(c2[nj][rr * 2 + 0], c2[nj][rr * 2 + 1]);
        }
    }
    __syncthreads();
    {
        int q = tid;
        #pragma unroll
        for (int t = 0; t < 4; t++, q += 256) {
            int r = q >> 5, c4 = (q & 31) * 4;
            float4 m = *(float4*)&smem[N2F_OUT + r * 132 + c4];
            size_t gi = (size_t)(r0 + r) * DD + nc + c4;
            float4 n4 = __ldg((const float4*)&nodes[gi]);
            float4 b4 = __ldg((const float4*)&nb2[nc + c4]);
            *(float4*)&out_nodes[gi] = make_float4(n4.x + m.x + b4.x, n4.y + m.y + b4.y,
                                                   n4.z + m.z + b4.z, n4.w + m.w + b4.w);
        }
    }
}

// ============================================================
// Kernel 4: fp16 fused edge path; 3-stage cp.async W pipeline,
// warp-local row-coalesced NI/NJ/stats + LN passes.  2 CTAs/SM.
// ============================================================
#define F_NI   0                     // [512] floats
#define F_OUT  768                   // [64][68] floats (aliases H_E/H_W0, dead at epilogue)
#define H_E    1536                  // half idx: [64][72]
#define H_W0   (H_E + 64 * 72)       // 3 W buffers of [64][72]
#define H_HE   (H_W0 + 3 * 64 * 72)  // [64][520]
#define EDGE_SMEM_BYTES ((H_HE + 64 * 520) * 2)

__global__ __launch_bounds__(256, 2) void k_edge_mma(
    const float* __restrict__ edges,
    const float* __restrict__ eg,
    const float* __restrict__ ebt,
    const float* __restrict__ eb2,
    float* __restrict__ out_edges)
{
    extern __shared__ float smem[];
    __half* sh = (__half*)smem;
    const uint32_t sb = (uint32_t)__cvta_generic_to_shared(smem);
    const int tid = threadIdx.x;
    const int w = tid >> 5, lane = tid & 31;
    const int g = lane >> 2, tig = lane & 3;
    const int mt = (w & 3) * 16, ntw = (w >> 2) * 32;
    const int b = blockIdx.z, i = blockIdx.y;
    const int j0 = blockIdx.x * JT;

    const int arow = lane & 15, ak8 = (lane >> 4) << 3;
    const int bn = (lane & 7) + ((lane >> 4) << 3);
    const int bk8 = ((lane >> 3) & 1) << 3;

    const __half* njb = g_NJh + (size_t)((size_t)b * NN + j0) * HH;

    #define W_ISSUE(src, ch, s) do { \
        _Pragma("unroll") \
        for (int t_ = 0; t_ < 2; t_++) { \
            int q_ = t_ * 256 + tid; \
            int n_ = q_ >> 3, k8_ = (q_ & 7) * 8; \
            cp16(sb + 2 * (H_W0 + (s) * 4608 + n_ * 72 + k8_), \
                 (src) + (ch) * 4096 + n_ * 64 + k8_); \
        } \
        CP_COMMIT(); \
    } while (0)

    // ---- stage E [64][72] fp16 ----
    const float* etile = edges + ((size_t)((size_t)b * NN + i) * NN + j0) * EE;
    #pragma unroll
    for (int t = 0; t < 4; t++) {
        int q = t * 256 + tid;
        int j = q >> 4, k0 = (q & 15) * 4;
        float4 v = __ldg((const float4*)&etile[j * EE + k0]);
        *(uint2*)&sh[H_E + j * 72 + k0] = make_uint2(pack2(v.x, v.y), pack2(v.z, v.w));
    }
    // ---- NI cache ----
    const float* nip = g_NI + (size_t)((size_t)b * NN + i) * HH;
    smem[F_NI + tid] = __ldg(&nip[tid]);
    smem[F_NI + 256 + tid] = __ldg(&nip[256 + tid]);

    W_ISSUE(g_w1h, 0, 0);
    __syncthreads();                           // E + NI visible

    // ---- hoist E fragments ----
    uint32_t ef[4][4];
    #pragma unroll
    for (int ks = 0; ks < 4; ks++)
        ldm_x4(ef[ks][0], ef[ks][1], ef[ks][2], ef[ks][3],
               sb + 2 * (H_E + (mt + arow) * 72 + ks * 16 + ak8));

    W_ISSUE(g_w1h, 1, 1);

    // ================= GEMM1: raw he = E@We -> sHe =========================
    for (int ch = 0; ch < 8; ch++) {
        if (ch < 7) CP_WAIT1(); else CP_WAIT0();
        __syncthreads();
        if (ch + 2 < 8) W_ISSUE(g_w1h, ch + 2, (ch + 2) % 3);
        const int bufo = H_W0 + (ch % 3) * 4608;
        float c[4][4];
        #pragma unroll
        for (int nj = 0; nj < 4; nj++)
            #pragma unroll
            for (int x = 0; x < 4; x++) c[nj][x] = 0.f;
        #pragma unroll
        for (int ks = 0; ks < 4; ks++) {
            int k0 = ks * 16;
            uint32_t p0, p1, p2, p3, q0, q1, q2, q3;
            ldm_x4(p0, p1, p2, p3, sb + 2 * (bufo + (ntw + bn) * 72 + k0 + bk8));
            ldm_x4(q0, q1, q2, q3, sb + 2 * (bufo + (ntw + 16 + bn) * 72 + k0 + bk8));
            mma_f16(c[0], ef[ks][0], ef[ks][1], ef[ks][2], ef[ks][3], p0, p1);
            mma_f16(c[1], ef[ks][0], ef[ks][1], ef[ks][2], ef[ks][3], p2, p3);
            mma_f16(c[2], ef[ks][0], ef[ks][1], ef[ks][2], ef[ks][3], q0, q1);
            mma_f16(c[3], ef[ks][0], ef[ks][1], ef[ks][2], ef[ks][3], q2, q3);
        }
        #pragma unroll
        for (int nj = 0; nj < 4; nj++) {
            int cl = ntw + nj * 8 + 2 * tig;
            #pragma unroll
            for (int rr = 0; rr < 2; rr++) {
                int row = mt + g + rr * 8;
                *(uint32_t*)&sh[H_HE + row * 520 + ch * 64 + cl] =
                    pack2(c[nj][rr * 2 + 0], c[nj][rr * 2 + 1]);
            }
        }
    }
    __syncthreads();                           // all raw he visible

    // issue W2 chunks 0,1 early (overlap the two row passes)
    W_ISSUE(g_w2h, 0, 0);
    W_ISSUE(g_w2h, 1, 1);

    // ---- warp-local pass A: he += NI + NJ (row-coalesced), stats ----
    {
        const int wr = w * 8;                  // this warp's 8 rows
        float s8[8], q8[8];
        #pragma unroll
        for (int r = 0; r < 8; r++) { s8[r] = 0.f; q8[r] = 0.f; }
        #pragma unroll
        for (int pass = 0; pass < 2; pass++) {
            int cb = pass * 256 + lane * 8;
            float4 ni0 = *(float4*)&smem[F_NI + cb];
            float4 ni1 = *(float4*)&smem[F_NI + cb + 4];
            #pragma unroll
            for (int r = 0; r < 8; r++) {
                int row = wr + r;
                uint4 m4 = *(uint4*)&sh[H_HE + row * 520 + cb];
                uint4 n4 = __ldg((const uint4*)&njb[(size_t)row * HH + cb]);
                float2 a, nv;
                a = h2f(m4.x); nv = h2f(n4.x);
                float v0 = a.x + ni0.x + nv.x, v1 = a.y + ni0.y + nv.y;
                a = h2f(m4.y); nv = h2f(n4.y);
                float v2 = a.x + ni0.z + nv.x, v3 = a.y + ni0.w + nv.y;
                a = h2f(m4.z); nv = h2f(n4.z);
                float v4 = a.x + ni1.x + nv.x, v5 = a.y + ni1.y + nv.y;
                a = h2f(m4.w); nv = h2f(n4.w);
                float v6 = a.x + ni1.z + nv.x, v7 = a.y + ni1.w + nv.y;
                s8[r] += v0 + v1 + v2 + v3 + v4 + v5 + v6 + v7;
                q8[r] += v0*v0 + v1*v1 + v2*v2 + v3*v3 + v4*v4 + v5*v5 + v6*v6 + v7*v7;
                m4.x = pack2(v0, v1); m4.y = pack2(v2, v3);
                m4.z = pack2(v4, v5); m4.w = pack2(v6, v7);
                *(uint4*)&sh[H_HE + row * 520 + cb] = m4;
            }
        }
        float mus[8], rss[8];
        #pragma unroll
        for (int r = 0; r < 8; r++) {
            float s = s8[r], q2 = q8[r];
            #pragma unroll
            for (int m = 16; m >= 1; m >>= 1) {
                s  += __shfl_xor_sync(0xffffffffu, s, m);
                q2 += __shfl_xor_sync(0xffffffffu, q2, m);
            }
            float mu = s * (1.f / HH);
            mus[r] = mu;
            rss[r] = rsqrtf(q2 * (1.f / HH) - mu * mu + 1e-5f);
        }

        // ---- warp-local LN + relu sweep ----
        #pragma unroll
        for (int pass = 0; pass < 2; pass++) {
            int cb = pass * 256 + lane * 8;
            float4 g0 = __ldg((const float4*)&eg[cb]);
            float4 g1 = __ldg((const float4*)&eg[cb + 4]);
            float4 t0 = __ldg((const float4*)&ebt[cb]);
            float4 t1 = __ldg((const float4*)&ebt[cb + 4]);
            #pragma unroll
            for (int r = 0; r < 8; r++) {
                int row = wr + r;
                float mu = mus[r], rs = rss[r];
                uint4 u = *(uint4*)&sh[H_HE + row * 520 + cb];
                float2 v;
                v = h2f(u.x);
                u.x = pack2(fmaxf((v.x - mu) * rs * g0.x + t0.x, 0.f),
                            fmaxf((v.y - mu) * rs * g0.y + t0.y, 0.f));
                v = h2f(u.y);
                u.y = pack2(fmaxf((v.x - mu) * rs * g0.z + t0.z, 0.f),
                            fmaxf((v.y - mu) * rs * g0.w + t0.w, 0.f));
                v = h2f(u.z);
                u.z = pack2(fmaxf((v.x - mu) * rs * g1.x + t1.x, 0.f),
                            fmaxf((v.y - mu) * rs * g1.y + t1.y, 0.f));
                v = h2f(u.w);
                u.w = pack2(fmaxf((v.x - mu) * rs * g1.z + t1.z, 0.f),
                            fmaxf((v.y - mu) * rs * g1.w + t1.w, 0.f));
                *(uint4*)&sh[H_HE + row * 520 + cb] = u;
            }
        }
    }

    // ================= GEMM2: out = ln_relu_he @ ew2 =======================
    float c2[4][4];
    #pragma unroll
    for (int nj = 0; nj < 4; nj++)
        #pragma unroll
        for (int x = 0; x < 4; x++) c2[nj][x] = 0.f;

    for (int kc = 0; kc < 8; kc++) {
        if (kc < 7) CP_WAIT1(); else CP_WAIT0();
        __syncthreads();                       // also orders LN writes before reads
        if (kc + 2 < 8) W_ISSUE(g_w2h, kc + 2, (kc + 2) % 3);
        const int bufo = H_W0 + (kc % 3) * 4608;
        #pragma unroll
        for (int ks = 0; ks < 4; ks++) {
            int k0 = ks * 16;
            uint32_t a0, a1, a2, a3, p0, p1, p2, p3, q0, q1, q2, q3;
            ldm_x4(a0, a1, a2, a3,
                   sb + 2 * (H_HE + (mt + arow) * 520 + kc * 64 + k0 + ak8));
            ldm_x4(p0, p1, p2, p3, sb + 2 * (bufo + (ntw + bn) * 72 + k0 + bk8));
            ldm_x4(q0, q1, q2, q3, sb + 2 * (bufo + (ntw + 16 + bn) * 72 + k0 + bk8));
            mma_f16(c2[0], a0, a1, a2, a3, p0, p1);
            mma_f16(c2[1], a0, a1, a2, a3, p2, p3);
            mma_f16(c2[2], a0, a1, a2, a3, q0, q1);
            mma_f16(c2[3], a0, a1, a2, a3, q2, q3);
        }
    }
    __syncthreads();

    // ---- epilogue: bounce via smem, coalesced residual + store ----
    #pragma unroll
    for (int nj = 0; nj < 4; nj++) {
        int cl = ntw + nj * 8 + 2 * tig;
        #pragma unroll
        for (int rr = 0; rr < 2; rr++) {
            int row = mt + g + rr * 8;
            *(float2*)&smem[F_OUT + row * 68 + cl] =
                make_float2(c2[nj][rr * 2 + 0], c2[nj][rr * 2 + 1]);
        }
    }
    __syncthreads();
    #pragma unroll
    for (int t = 0; t < 4; t++) {
        int q = t * 256 + tid;
        int r = q >> 4, c4 = (q & 15) * 4;
        float4 m = *(float4*)&smem[F_OUT + r * 68 + c4];
        size_t gbase = ((size_t)((size_t)b * NN + i) * NN + j0 + r) * EE + c4;
        float4 e4 = __ldg((const float4*)&edges[gbase]);
        float4 b4 = __ldg((const float4*)&eb2[c4]);
        float4 o = make_float4(e4.x + m.x + b4.x, e4.y + m.y + b4.y,
                               e4.z + m.z + b4.z, e4.w + m.w + b4.w);
        *(float4*)&out_edges[gbase] = o;
    }
}

// ============================================================
extern "C" void kernel_launch(void* const* d_in, const int* in_sizes, int n_in,
                              void* d_out, int out_size)
{
    const float* nodes = (const float*)d_in[0];
    const float* edges = (const float*)d_in[1];
    const float* adj   = (const float*)d_in[2];
    const float* nw1   = (const float*)d_in[3];
    const float* nb1   = (const float*)d_in[4];
    const float* ng    = (const float*)d_in[5];
    const float* nbt   = (const float*)d_in[6];
    const float* nw2   = (const float*)d_in[7];
    const float* nb2   = (const float*)d_in[8];
    const float* ew1   = (const float*)d_in[9];
    const float* eb1   = (const float*)d_in[10];
    const float* eg    = (const float*)d_in[11];
    const float* ebt   = (const float*)d_in[12];
    const float* ew2   = (const float*)d_in[13];
    const float* eb2   = (const float*)d_in[14];

    float* out_nodes = (float*)d_out;
    float* out_edges = out_nodes + (size_t)BB * NN * DD;

    cudaFuncSetAttribute(k_edge_mma, cudaFuncAttributeMaxDynamicSharedMemorySize,
                         EDGE_SMEM_BYTES);
    cudaFuncSetAttribute(k_ninj_mma, cudaFuncAttributeMaxDynamicSharedMemorySize,
                         NINJ_SMEM_BYTES);
    cudaFuncSetAttribute(k_node1, cudaFuncAttributeMaxDynamicSharedMemorySize,
                         N1_SMEM_BYTES);
    cudaFuncSetAttribute(k_node2, cudaFuncAttributeMaxDynamicSharedMemorySize,
                         N2_SMEM_BYTES);

    static cudaStream_t s2 = nullptr;
    static cudaEvent_t evFork = nullptr, evJoin = nullptr;
    if (s2 == nullptr) {
        if (cudaStreamCreateWithFlags(&s2, cudaStreamNonBlocking) != cudaSuccess)
            s2 = nullptr;
        if (s2) {
            cudaEventCreateWithFlags(&evFork, cudaEventDisableTiming);
            cudaEventCreateWithFlags(&evJoin, cudaEventDisableTiming);
        }
    }

    if (s2) {
        cudaEventRecord(evFork, 0);
        cudaStreamWaitEvent(s2, evFork, 0);
        k_node1<<<48, 256, N1_SMEM_BYTES, s2>>>(nodes, edges, adj, nw1, nb1, ng, nbt);
        k_node2<<<dim3(6, 24), 256, N2_SMEM_BYTES, s2>>>(nodes, nw2, nb2, out_nodes);
        cudaEventRecord(evJoin, s2);
        k_prep<<<296, 256>>>(nodes, ew1, ew2);
        k_ninj_mma<<<dim3(8, 48), 256, NINJ_SMEM_BYTES>>>(eb1);
        k_edge_mma<<<dim3(NN / JT, NN, BB), 256, EDGE_SMEM_BYTES>>>(edges, eg, ebt, eb2, out_edges);
        cudaStreamWaitEvent(0, evJoin, 0);
    } else {
        k_prep<<<296, 256>>>(nodes, ew1, ew2);
        k_ninj_mma<<<dim3(8, 48), 256, NINJ_SMEM_BYTES>>>(eb1);
        k_node1<<<48, 256, N1_SMEM_BYTES>>>(nodes, edges, adj, nw1, nb1, ng, nbt);
        k_node2<<<dim3(6, 24), 256, N2_SMEM_BYTES>>>(nodes, nw2, nb2, out_nodes);
        k_edge_mma<<<dim3(NN / JT, NN, BB), 256, EDGE_SMEM_BYTES>>>(edges, eg, ebt, eb2, out_edges);
    }
}